// round 12
// baseline (speedup 1.0000x reference)
#include <cuda_runtime.h>
#include <cuda_bf16.h>
#include <cuda_fp16.h>
#include <cstdint>

// Problem constants
#define B 2
#define S 2048
#define E 2048
#define HQ 32
#define HK 8
#define D 64

// ---------------------------------------------------------------------------
// Scratch (device globals)
// ---------------------------------------------------------------------------
__device__ __nv_bfloat16 g_xhi[(size_t)B * S * E];
__device__ __nv_bfloat16 g_xlo[(size_t)B * S * E];
__device__ __half        g_xh[(size_t)B * S * E];        // x fp16 (for v-proj)
__device__ __nv_bfloat16 g_wqkhi[(size_t)2560 * E];      // [N=2560, K=2048]
__device__ __nv_bfloat16 g_wqklo[(size_t)2560 * E];
__device__ __half        g_wvh[(size_t)512 * E];         // Wv^T fp16
__device__ __half        g_wohf[(size_t)E * HQ * D];     // Wo^T fp16

__device__ __nv_bfloat16 g_qhi[(size_t)B * S * HQ * D]; // post-RoPE bf16
__device__ __nv_bfloat16 g_qlo[(size_t)B * S * HQ * D];
__device__ __nv_bfloat16 g_khi[(size_t)B * S * HK * D];
__device__ __nv_bfloat16 g_klo[(size_t)B * S * HK * D];
__device__ __half        g_vh[(size_t)B * S * HK * D];  // v fp16 (from GEMM)
__device__ __half        g_of[(size_t)B * S * HQ * D];  // attention out, fp16

// ---------------------------------------------------------------------------
// PTX helpers (base-target safe)
// ---------------------------------------------------------------------------
__device__ __forceinline__ uint32_t smem_u32(const void* p) {
    uint32_t a;
    asm("{ .reg .u64 t; cvta.to.shared.u64 t, %1; cvt.u32.u64 %0, t; }"
        : "=r"(a) : "l"(p));
    return a;
}
__device__ __forceinline__ void cp16(uint32_t dst, const void* src) {
    asm volatile("cp.async.cg.shared.global [%0], [%1], 16;"
                 :: "r"(dst), "l"(src) : "memory");
}
__device__ __forceinline__ void cp_commit() {
    asm volatile("cp.async.commit_group;" ::: "memory");
}
template <int N>
__device__ __forceinline__ void cp_wait() {
    asm volatile("cp.async.wait_group %0;" :: "n"(N) : "memory");
}
__device__ __forceinline__ void ldm4(uint32_t* r, uint32_t addr) {
    asm volatile("ldmatrix.sync.aligned.m8n8.x4.shared.b16 {%0,%1,%2,%3}, [%4];"
                 : "=r"(r[0]), "=r"(r[1]), "=r"(r[2]), "=r"(r[3]) : "r"(addr));
}
__device__ __forceinline__ void ldm4t(uint32_t* r, uint32_t addr) {
    asm volatile("ldmatrix.sync.aligned.m8n8.x4.trans.shared.b16 {%0,%1,%2,%3}, [%4];"
                 : "=r"(r[0]), "=r"(r[1]), "=r"(r[2]), "=r"(r[3]) : "r"(addr));
}
__device__ __forceinline__ void mma_bf16(float* c, const uint32_t* a,
                                         const uint32_t* b) {
    asm volatile(
        "mma.sync.aligned.m16n8k16.row.col.f32.bf16.bf16.f32 "
        "{%0,%1,%2,%3}, {%4,%5,%6,%7}, {%8,%9}, {%0,%1,%2,%3};"
        : "+f"(c[0]), "+f"(c[1]), "+f"(c[2]), "+f"(c[3])
        : "r"(a[0]), "r"(a[1]), "r"(a[2]), "r"(a[3]), "r"(b[0]), "r"(b[1]));
}
__device__ __forceinline__ void mma_f16(float* c, const uint32_t* a,
                                        const uint32_t* b) {
    asm volatile(
        "mma.sync.aligned.m16n8k16.row.col.f32.f16.f16.f32 "
        "{%0,%1,%2,%3}, {%4,%5,%6,%7}, {%8,%9}, {%0,%1,%2,%3};"
        : "+f"(c[0]), "+f"(c[1]), "+f"(c[2]), "+f"(c[3])
        : "r"(a[0]), "r"(a[1]), "r"(a[2]), "r"(a[3]), "r"(b[0]), "r"(b[1]));
}
__device__ __forceinline__ uint32_t packbf(__nv_bfloat16 a, __nv_bfloat16 b) {
    __nv_bfloat162 t = __halves2bfloat162(a, b);
    return *(uint32_t*)&t;
}
__device__ __forceinline__ uint32_t packh(float x, float y) {
    __half2 t = __floats2half2_rn(x, y);
    return *(uint32_t*)&t;
}
__device__ __forceinline__ void split2(float x, float y,
                                       uint32_t& hi, uint32_t& lo) {
    __nv_bfloat16 hx = __float2bfloat16(x), hy = __float2bfloat16(y);
    __nv_bfloat16 lx = __float2bfloat16(x - __bfloat162float(hx));
    __nv_bfloat16 ly = __float2bfloat16(y - __bfloat162float(hy));
    hi = packbf(hx, hy);
    lo = packbf(lx, ly);
}

// ---------------------------------------------------------------------------
// Split fp32 -> bf16 hi/lo + fp16 single
// ---------------------------------------------------------------------------
__global__ void split3_kernel(const float* __restrict__ src,
                              __nv_bfloat16* __restrict__ hi,
                              __nv_bfloat16* __restrict__ lo,
                              __half* __restrict__ hf, int n4)
{
    int i = blockIdx.x * blockDim.x + threadIdx.x;
    if (i >= n4) return;
    float4 v = ((const float4*)src)[i];
    uint32_t h0, l0, h1, l1;
    split2(v.x, v.y, h0, l0);
    split2(v.z, v.w, h1, l1);
    ((uint32_t*)hi)[2*i]   = h0;
    ((uint32_t*)hi)[2*i+1] = h1;
    ((uint32_t*)lo)[2*i]   = l0;
    ((uint32_t*)lo)[2*i+1] = l1;
    ((uint32_t*)hf)[2*i]   = packh(v.x, v.y);
    ((uint32_t*)hf)[2*i+1] = packh(v.z, v.w);
}

// ---------------------------------------------------------------------------
// Transpose W[K,N] -> Wt[N,K], bf16 hi/lo
// ---------------------------------------------------------------------------
__global__ __launch_bounds__(256) void transpose_split_kernel(
    const float* __restrict__ W,
    __nv_bfloat16* __restrict__ hiT,
    __nv_bfloat16* __restrict__ loT, int K, int N)
{
    __shared__ float t[32][33];
    int n0 = blockIdx.x * 32, k0 = blockIdx.y * 32;
    int tx = threadIdx.x, ty = threadIdx.y;
#pragma unroll
    for (int r = 0; r < 4; r++)
        t[ty + r*8][tx] = W[(size_t)(k0 + ty + r*8) * N + n0 + tx];
    __syncthreads();
#pragma unroll
    for (int r = 0; r < 4; r++) {
        int n = n0 + ty + r*8;
        float v = t[tx][ty + r*8];
        __nv_bfloat16 h = __float2bfloat16(v);
        hiT[(size_t)n * K + k0 + tx] = h;
        loT[(size_t)n * K + k0 + tx] = __float2bfloat16(v - __bfloat162float(h));
    }
}

// Transpose W[K,N] -> Wt[N,K], single fp16
__global__ __launch_bounds__(256) void transpose_h_kernel(
    const float* __restrict__ W,
    __half* __restrict__ hT, int K, int N)
{
    __shared__ float t[32][33];
    int n0 = blockIdx.x * 32, k0 = blockIdx.y * 32;
    int tx = threadIdx.x, ty = threadIdx.y;
#pragma unroll
    for (int r = 0; r < 4; r++)
        t[ty + r*8][tx] = W[(size_t)(k0 + ty + r*8) * N + n0 + tx];
    __syncthreads();
#pragma unroll
    for (int r = 0; r < 4; r++) {
        int n = n0 + ty + r*8;
        hT[(size_t)n * K + k0 + tx] = __float2half_rn(t[tx][ty + r*8]);
    }
}

// ---------------------------------------------------------------------------
// QK projection GEMM (bf16 3-term) with fused RoPE + bf16 hi/lo split
// epilogue. N=2560 (cols 0-2047: q heads, 2048-2559: k heads). 2 CTAs/SM.
// ---------------------------------------------------------------------------
#define TSTRIDE 80
#define TILE_BYTES (128 * TSTRIDE)
#define STAGE_BYTES (4 * TILE_BYTES)
#define GEMM_SMEM (2 * STAGE_BYTES)
#define SCS 129   // epilogue smem float stride (128x129x4 = 66048 B < 80K)

__device__ __forceinline__ void load_stage(
    uint32_t base, int tid,
    const __nv_bfloat16* Ah, const __nv_bfloat16* Al,
    const __nv_bfloat16* Bh, const __nv_bfloat16* Bl,
    int K, int k0)
{
    int ch = tid & 3;
    int rhalf = tid >> 2;
#pragma unroll
    for (int i = 0; i < 8; i++) {
        int tile = i >> 1;
        int row = (i & 1) * 64 + rhalf;
        uint32_t dst = base + tile * TILE_BYTES + row * TSTRIDE + ch * 16;
        const __nv_bfloat16* src =
            (tile == 0) ? Ah : (tile == 1) ? Al : (tile == 2) ? Bh : Bl;
        cp16(dst, src + (size_t)row * K + k0 + ch * 8);
    }
}

__global__ __launch_bounds__(256, 2) void mma_gemm_qk_kernel(
    const __nv_bfloat16* __restrict__ Ahi, const __nv_bfloat16* __restrict__ Alo,
    const __nv_bfloat16* __restrict__ Bhi, const __nv_bfloat16* __restrict__ Blo,
    const float* __restrict__ cs, const float* __restrict__ sn)
{
    const int K = E, N = 2560;
    extern __shared__ char smem[];
    uint32_t sb = smem_u32(smem);
    int tid = threadIdx.x;
    int lane = tid & 31, wid = tid >> 5;
    int wm = wid & 1, wn = wid >> 1;
    int bm = blockIdx.y * 128, bn = blockIdx.x * 128;

    const __nv_bfloat16* Ah = Ahi + (size_t)bm * K;
    const __nv_bfloat16* Al = Alo + (size_t)bm * K;
    const __nv_bfloat16* Bh = Bhi + (size_t)bn * K;
    const __nv_bfloat16* Bl = Blo + (size_t)bn * K;

    float acc[4][4][4];
#pragma unroll
    for (int i = 0; i < 4; i++)
#pragma unroll
        for (int j = 0; j < 4; j++)
#pragma unroll
            for (int r = 0; r < 4; r++) acc[i][j][r] = 0.f;

    uint32_t aoff = (uint32_t)((wm * 64 + (lane & 15)) * TSTRIDE + (lane >> 4) * 16);
    uint32_t boff = (uint32_t)((wn * 32 + ((lane >> 4) * 8) + (lane & 7)) * TSTRIDE
                               + ((lane >> 3) & 1) * 16);

    const int nch = K >> 5;
    load_stage(sb, tid, Ah, Al, Bh, Bl, K, 0);
    cp_commit();

    for (int ch = 0; ch < nch; ch++) {
        if (ch + 1 < nch) {
            load_stage(sb + ((ch + 1) & 1) * STAGE_BYTES, tid,
                       Ah, Al, Bh, Bl, K, (ch + 1) << 5);
            cp_commit();
            cp_wait<1>();
        } else {
            cp_wait<0>();
        }
        __syncthreads();

        uint32_t st = sb + (ch & 1) * STAGE_BYTES;
        uint32_t sAhi = st;
        uint32_t sAlo = st + TILE_BYTES;
        uint32_t sBhi = st + 2 * TILE_BYTES;
        uint32_t sBlo = st + 3 * TILE_BYTES;

#pragma unroll
        for (int ks = 0; ks < 2; ks++) {
            uint32_t kb = ks * 32;
            uint32_t bh[8], bl[8], a[16];
            ldm4(bh + 0, sBhi + boff + kb);
            ldm4(bh + 4, sBhi + boff + 16 * TSTRIDE + kb);
            ldm4(bl + 0, sBlo + boff + kb);
            ldm4(bl + 4, sBlo + boff + 16 * TSTRIDE + kb);
#pragma unroll
            for (int mt = 0; mt < 4; mt++)
                ldm4(a + 4 * mt, sAhi + aoff + mt * 16 * TSTRIDE + kb);
#pragma unroll
            for (int mt = 0; mt < 4; mt++)
#pragma unroll
                for (int nt = 0; nt < 4; nt++)
                    mma_bf16(acc[mt][nt], a + 4 * mt, bh + 2 * nt);
#pragma unroll
            for (int mt = 0; mt < 4; mt++)
#pragma unroll
                for (int nt = 0; nt < 4; nt++)
                    mma_bf16(acc[mt][nt], a + 4 * mt, bl + 2 * nt);
#pragma unroll
            for (int mt = 0; mt < 4; mt++)
                ldm4(a + 4 * mt, sAlo + aoff + mt * 16 * TSTRIDE + kb);
#pragma unroll
            for (int mt = 0; mt < 4; mt++)
#pragma unroll
                for (int nt = 0; nt < 4; nt++)
                    mma_bf16(acc[mt][nt], a + 4 * mt, bh + 2 * nt);
        }
        __syncthreads();
    }

    // ---- epilogue: stage tile to smem, then fused RoPE + split ----
    float* sc = (float*)smem;
    {
        int r0l = wm * 64 + (lane >> 2);
        int c0l = wn * 32 + (lane & 3) * 2;
#pragma unroll
        for (int mt = 0; mt < 4; mt++) {
#pragma unroll
            for (int nt = 0; nt < 4; nt++) {
                int rr = r0l + mt * 16;
                int cc = c0l + nt * 8;
                sc[rr * SCS + cc]       = acc[mt][nt][0];
                sc[rr * SCS + cc + 1]   = acc[mt][nt][1];
                sc[(rr+8) * SCS + cc]   = acc[mt][nt][2];
                sc[(rr+8) * SCS + cc+1] = acc[mt][nt][3];
            }
        }
    }
    __syncthreads();

    {
        int row = tid >> 1;            // 0..127
        int half = tid & 1;            // which 64-col head within tile
        int brow = bm + row;
        int s = brow & (S - 1);
        int gc0 = bn + half * 64;
        __nv_bfloat16 *hip, *lop;
        if (gc0 < 2048) {
            int head = gc0 >> 6;
            size_t o = ((size_t)brow * HQ + head) * 64;
            hip = g_qhi + o; lop = g_qlo + o;
        } else {
            int head = (gc0 - 2048) >> 6;
            size_t o = ((size_t)brow * HK + head) * 64;
            hip = g_khi + o; lop = g_klo + o;
        }
        const float* sr = sc + row * SCS + half * 64;
        const float* cp = cs + s * 32;
        const float* sp = sn + s * 32;
#pragma unroll
        for (int d = 0; d < 32; d += 2) {
            float v1a = sr[d],      v1b = sr[d + 1];
            float v2a = sr[d + 32], v2b = sr[d + 33];
            float ca = cp[d], cb = cp[d + 1];
            float sa = sp[d], sb2 = sp[d + 1];
            float r1a = v1a * ca - v2a * sa;
            float r1b = v1b * cb - v2b * sb2;
            float r2a = v2a * ca + v1a * sa;
            float r2b = v2b * cb + v1b * sb2;
            uint32_t h1, l1, h2, l2;
            split2(r1a, r1b, h1, l1);
            split2(r2a, r2b, h2, l2);
            *(uint32_t*)(hip + d)      = h1;
            *(uint32_t*)(hip + d + 32) = h2;
            *(uint32_t*)(lop + d)      = l1;
            *(uint32_t*)(lop + d + 32) = l2;
        }
    }
}

// ---------------------------------------------------------------------------
// fp16 single-term GEMM — 2 CTAs/SM
// ---------------------------------------------------------------------------
#define STAGE1_BYTES (2 * TILE_BYTES)
#define GEMM1_SMEM (2 * STAGE1_BYTES)

__device__ __forceinline__ void load_stage1(
    uint32_t base, int tid,
    const __half* A, const __half* Bh, int K, int k0)
{
    int ch = tid & 3;
    int rhalf = tid >> 2;
#pragma unroll
    for (int i = 0; i < 4; i++) {
        int tile = i >> 1;
        int row = (i & 1) * 64 + rhalf;
        uint32_t dst = base + tile * TILE_BYTES + row * TSTRIDE + ch * 16;
        const __half* src = (tile == 0) ? A : Bh;
        cp16(dst, src + (size_t)row * K + k0 + ch * 8);
    }
}

template <bool HALF_OUT>
__global__ __launch_bounds__(256, 2) void mma_gemm1_kernel(
    int M, int N, int K,
    const __half* __restrict__ A,
    const __half* __restrict__ Bhi,
    void* __restrict__ Cout)
{
    extern __shared__ char smem[];
    uint32_t sb = smem_u32(smem);
    int tid = threadIdx.x;
    int lane = tid & 31, wid = tid >> 5;
    int wm = wid & 1, wn = wid >> 1;
    int bm = blockIdx.y * 128, bn = blockIdx.x * 128;

    const __half* Ap = A + (size_t)bm * K;
    const __half* Bh = Bhi + (size_t)bn * K;

    float acc[4][4][4];
#pragma unroll
    for (int i = 0; i < 4; i++)
#pragma unroll
        for (int j = 0; j < 4; j++)
#pragma unroll
            for (int r = 0; r < 4; r++) acc[i][j][r] = 0.f;

    uint32_t aoff = (uint32_t)((wm * 64 + (lane & 15)) * TSTRIDE + (lane >> 4) * 16);
    uint32_t boff = (uint32_t)((wn * 32 + ((lane >> 4) * 8) + (lane & 7)) * TSTRIDE
                               + ((lane >> 3) & 1) * 16);

    const int nch = K >> 5;
    load_stage1(sb, tid, Ap, Bh, K, 0);
    cp_commit();

    for (int ch = 0; ch < nch; ch++) {
        if (ch + 1 < nch) {
            load_stage1(sb + ((ch + 1) & 1) * STAGE1_BYTES, tid,
                        Ap, Bh, K, (ch + 1) << 5);
            cp_commit();
            cp_wait<1>();
        } else {
            cp_wait<0>();
        }
        __syncthreads();

        uint32_t st = sb + (ch & 1) * STAGE1_BYTES;
        uint32_t sA = st;
        uint32_t sB = st + TILE_BYTES;

#pragma unroll
        for (int ks = 0; ks < 2; ks++) {
            uint32_t kb = ks * 32;
            uint32_t bh[8], a[16];
            ldm4(bh + 0, sB + boff + kb);
            ldm4(bh + 4, sB + boff + 16 * TSTRIDE + kb);
#pragma unroll
            for (int mt = 0; mt < 4; mt++)
                ldm4(a + 4 * mt, sA + aoff + mt * 16 * TSTRIDE + kb);
#pragma unroll
            for (int mt = 0; mt < 4; mt++)
#pragma unroll
                for (int nt = 0; nt < 4; nt++)
                    mma_f16(acc[mt][nt], a + 4 * mt, bh + 2 * nt);
        }
        __syncthreads();
    }

    int r0 = bm + wm * 64 + (lane >> 2);
    int c0 = bn + wn * 32 + (lane & 3) * 2;
#pragma unroll
    for (int mt = 0; mt < 4; mt++) {
#pragma unroll
        for (int nt = 0; nt < 4; nt++) {
            int row = r0 + mt * 16;
            int col = c0 + nt * 8;
            if (HALF_OUT) {
                __half* C = (__half*)Cout;
                *(uint32_t*)&C[(size_t)row * N + col] =
                    packh(acc[mt][nt][0], acc[mt][nt][1]);
                *(uint32_t*)&C[(size_t)(row + 8) * N + col] =
                    packh(acc[mt][nt][2], acc[mt][nt][3]);
            } else {
                float* C = (float*)Cout;
                *(float2*)&C[(size_t)row * N + col] =
                    make_float2(acc[mt][nt][0], acc[mt][nt][1]);
                *(float2*)&C[(size_t)(row + 8) * N + col] =
                    make_float2(acc[mt][nt][2], acc[mt][nt][3]);
            }
        }
    }
}

// ---------------------------------------------------------------------------
// Tensor-core flash attention — 2 CTAs/SM.
// QK: bf16 3-term. PV: p fp16 x v fp16 (1 term). fp16 out.
// ---------------------------------------------------------------------------
#define FSTRIDE 144
#define FTILE (64 * FSTRIDE)
#define FSTAGE (3 * FTILE)              // khi, klo, vh
#define QTILE (128 * FSTRIDE)
#define FLASH_SMEM (2 * FSTAGE)         // 55296

__global__ __launch_bounds__(256, 2) void flash_mma_kernel()
{
    extern __shared__ char smem[];
    uint32_t sb = smem_u32(smem);
    int tid = threadIdx.x;
    int lane = tid & 31, wq = tid >> 5;
    int qbase = blockIdx.x * 128;
    int h = blockIdx.y, b = blockIdx.z;
    int kh = h >> 2;

    // ---- stage Q hi/lo, build fragments ----
#pragma unroll
    for (int i = 0; i < 8; i++) {
        int lin = i * 256 + tid;
        int arr = lin >> 10;
        int rem = lin & 1023;
        int row = rem >> 3;
        int seg = rem & 7;
        const __nv_bfloat16* src = arr ? g_qlo : g_qhi;
        cp16(sb + arr * QTILE + row * FSTRIDE + seg * 16,
             src + ((size_t)(b * S + qbase + row) * HQ + h) * 64 + seg * 8);
    }
    cp_commit();
    cp_wait<0>();
    __syncthreads();

    uint32_t qhi[4][4], qlo[4][4];
    {
        uint32_t qoff = (uint32_t)((wq * 16 + (lane & 15)) * FSTRIDE + (lane >> 4) * 16);
#pragma unroll
        for (int ks = 0; ks < 4; ks++) {
            ldm4(qhi[ks], sb + qoff + ks * 32);
            ldm4(qlo[ks], sb + QTILE + qoff + ks * 32);
        }
    }
    __syncthreads();

    // ---- kv staging (3 arrays: khi, klo bf16; vh fp16) ----
    const uint8_t* srcs[3];
    srcs[0] = (const uint8_t*)(g_khi + ((size_t)b * S * HK + kh) * D);
    srcs[1] = (const uint8_t*)(g_klo + ((size_t)b * S * HK + kh) * D);
    srcs[2] = (const uint8_t*)(g_vh + ((size_t)b * S * HK + kh) * D);

    auto prefetch = [&](int t) {
        uint32_t base = sb + (t & 1) * FSTAGE;
        int key0 = t * 64;
#pragma unroll
        for (int i = 0; i < 6; i++) {
            int lin = i * 256 + tid;
            int arr = lin >> 9;
            int rem = lin & 511;
            int row = rem >> 3;
            int seg = rem & 7;
            cp16(base + arr * FTILE + row * FSTRIDE + seg * 16,
                 srcs[arr] + (size_t)(key0 + row) * (HK * D * 2) + seg * 16);
        }
        cp_commit();
    };

    uint32_t boff = (uint32_t)(((lane >> 4) * 8 + (lane & 7)) * FSTRIDE
                               + ((lane >> 3) & 1) * 16);
    uint32_t voff = (uint32_t)((lane & 15) * FSTRIDE + (lane >> 4) * 16);

    float o_[8][4];
#pragma unroll
    for (int nt = 0; nt < 8; nt++)
#pragma unroll
        for (int r = 0; r < 4; r++) o_[nt][r] = 0.f;
    float m0 = -1e30f, m1 = -1e30f, l0 = 0.f, l1 = 0.f;

    prefetch(0);

    const int NT = S / 64;
    for (int t = 0; t < NT; t++) {
        if (t + 1 < NT) { prefetch(t + 1); cp_wait<1>(); }
        else           { cp_wait<0>(); }
        __syncthreads();

        uint32_t st = sb + (t & 1) * FSTAGE;
        uint32_t sKhi = st, sKlo = st + FTILE;
        uint32_t sVh = st + 2 * FTILE;

        float s[8][4];
#pragma unroll
        for (int nt = 0; nt < 8; nt++)
#pragma unroll
            for (int r = 0; r < 4; r++) s[nt][r] = 0.f;

        // QK, processed in two 4-nt halves (reduced b-frag live range)
#pragma unroll
        for (int ks = 0; ks < 4; ks++) {
            uint32_t kb = ks * 32;
#pragma unroll
            for (int hf = 0; hf < 2; hf++) {
                uint32_t rb = hf * 32 * FSTRIDE;
                uint32_t bh[8], bl[8];
                ldm4(bh + 0, sKhi + boff + rb + kb);
                ldm4(bh + 4, sKhi + boff + rb + 16 * FSTRIDE + kb);
                ldm4(bl + 0, sKlo + boff + rb + kb);
                ldm4(bl + 4, sKlo + boff + rb + 16 * FSTRIDE + kb);
#pragma unroll
                for (int j = 0; j < 4; j++) {
                    int nt = hf * 4 + j;
                    mma_bf16(s[nt], qhi[ks], bh + 2*j);
                    mma_bf16(s[nt], qhi[ks], bl + 2*j);
                    mma_bf16(s[nt], qlo[ks], bh + 2*j);
                }
            }
        }

        float tmax0 = -1e30f, tmax1 = -1e30f;
#pragma unroll
        for (int nt = 0; nt < 8; nt++) {
            tmax0 = fmaxf(tmax0, fmaxf(s[nt][0], s[nt][1]));
            tmax1 = fmaxf(tmax1, fmaxf(s[nt][2], s[nt][3]));
        }
        tmax0 = fmaxf(tmax0, __shfl_xor_sync(0xffffffffu, tmax0, 1));
        tmax0 = fmaxf(tmax0, __shfl_xor_sync(0xffffffffu, tmax0, 2));
        tmax1 = fmaxf(tmax1, __shfl_xor_sync(0xffffffffu, tmax1, 1));
        tmax1 = fmaxf(tmax1, __shfl_xor_sync(0xffffffffu, tmax1, 2));
        float nm0 = fmaxf(m0, tmax0), nm1 = fmaxf(m1, tmax1);
        float a0 = __expf(m0 - nm0), a1 = __expf(m1 - nm1);
        m0 = nm0; m1 = nm1;
        float ps0 = 0.f, ps1 = 0.f;
#pragma unroll
        for (int nt = 0; nt < 8; nt++) {
            s[nt][0] = __expf(s[nt][0] - m0);
            s[nt][1] = __expf(s[nt][1] - m0);
            s[nt][2] = __expf(s[nt][2] - m1);
            s[nt][3] = __expf(s[nt][3] - m1);
            ps0 += s[nt][0] + s[nt][1];
            ps1 += s[nt][2] + s[nt][3];
        }
        l0 = l0 * a0 + ps0;
        l1 = l1 * a1 + ps1;
#pragma unroll
        for (int nt = 0; nt < 8; nt++) {
            o_[nt][0] *= a0; o_[nt][1] *= a0;
            o_[nt][2] *= a1; o_[nt][3] *= a1;
        }

        // ---- PV: p fp16 x v fp16, single term ----
#pragma unroll
        for (int ks = 0; ks < 4; ks++) {
            uint32_t ph[4];
            ph[0] = packh(s[2*ks][0],   s[2*ks][1]);
            ph[1] = packh(s[2*ks][2],   s[2*ks][3]);
            ph[2] = packh(s[2*ks+1][0], s[2*ks+1][1]);
            ph[3] = packh(s[2*ks+1][2], s[2*ks+1][3]);
            uint32_t rbase = ks * 16 * FSTRIDE;
#pragma unroll
            for (int n2 = 0; n2 < 4; n2++) {
                uint32_t vh[4];
                ldm4t(vh, sVh + voff + rbase + n2 * 32);
                mma_f16(o_[2*n2],     ph, vh + 0);
                mma_f16(o_[2*n2 + 1], ph, vh + 2);
            }
        }
        __syncthreads();
    }

    // ---- finalize: write single fp16 ----
    l0 += __shfl_xor_sync(0xffffffffu, l0, 1);
    l0 += __shfl_xor_sync(0xffffffffu, l0, 2);
    l1 += __shfl_xor_sync(0xffffffffu, l1, 1);
    l1 += __shfl_xor_sync(0xffffffffu, l1, 2);
    float inv0 = 1.f / l0, inv1 = 1.f / l1;

    int r = qbase + wq * 16 + (lane >> 2);
    int c = (lane & 3) * 2;
    size_t ob0 = ((size_t)(b * S + r) * HQ + h) * D;
    size_t ob1 = ((size_t)(b * S + r + 8) * HQ + h) * D;
#pragma unroll
    for (int nt = 0; nt < 8; nt++) {
        *(uint32_t*)(g_of + ob0 + nt * 8 + c) =
            packh(o_[nt][0] * inv0, o_[nt][1] * inv0);
        *(uint32_t*)(g_of + ob1 + nt * 8 + c) =
            packh(o_[nt][2] * inv1, o_[nt][3] * inv1);
    }
}

// ---------------------------------------------------------------------------
// Launch
// ---------------------------------------------------------------------------
extern "C" void kernel_launch(void* const* d_in, const int* in_sizes, int n_in,
                              void* d_out, int out_size)
{
    const float* x    = (const float*)d_in[0];
    const float* rcos = (const float*)d_in[1];
    const float* rsin = (const float*)d_in[2];
    const float* Wq   = (const float*)d_in[4];
    const float* Wk   = (const float*)d_in[5];
    const float* Wv   = (const float*)d_in[6];
    const float* Wo   = (const float*)d_in[7];
    float* out = (float*)d_out;

    __nv_bfloat16 *xhi, *xlo, *wqkhi, *wqklo;
    __half *xh, *wvh, *wohf, *vhp, *ofp;
    cudaGetSymbolAddress((void**)&xhi, g_xhi);
    cudaGetSymbolAddress((void**)&xlo, g_xlo);
    cudaGetSymbolAddress((void**)&xh, g_xh);
    cudaGetSymbolAddress((void**)&wqkhi, g_wqkhi);
    cudaGetSymbolAddress((void**)&wqklo, g_wqklo);
    cudaGetSymbolAddress((void**)&wvh, g_wvh);
    cudaGetSymbolAddress((void**)&wohf, g_wohf);
    cudaGetSymbolAddress((void**)&vhp, g_vh);
    cudaGetSymbolAddress((void**)&ofp, g_of);

    cudaFuncSetAttribute(mma_gemm_qk_kernel,
                         cudaFuncAttributeMaxDynamicSharedMemorySize, GEMM_SMEM);
    cudaFuncSetAttribute(mma_gemm1_kernel<false>,
                         cudaFuncAttributeMaxDynamicSharedMemorySize, GEMM1_SMEM);
    cudaFuncSetAttribute(mma_gemm1_kernel<true>,
                         cudaFuncAttributeMaxDynamicSharedMemorySize, GEMM1_SMEM);
    cudaFuncSetAttribute(flash_mma_kernel,
                         cudaFuncAttributeMaxDynamicSharedMemorySize, FLASH_SMEM);

    const int M = B * S;  // 4096

    // 0) split x -> bf16 hi/lo + fp16
    {
        int n4 = M * E / 4;
        split3_kernel<<<(n4 + 255) / 256, 256>>>(x, xhi, xlo, xh, n4);
    }
    // 1-2) transpose+split Wq/Wk (bf16) into concatenated [2560, 2048]
    transpose_split_kernel<<<dim3((HQ*D)/32, E/32), dim3(32, 8)>>>(
        Wq, wqkhi, wqklo, E, HQ*D);
    transpose_split_kernel<<<dim3((HK*D)/32, E/32), dim3(32, 8)>>>(
        Wk, wqkhi + (size_t)2048 * E, wqklo + (size_t)2048 * E, E, HK*D);
    // 3) transpose Wv (fp16), 4) transpose Wo (fp16)
    transpose_h_kernel<<<dim3((HK*D)/32, E/32), dim3(32, 8)>>>(Wv, wvh, E, HK*D);
    transpose_h_kernel<<<dim3(E/32, (HQ*D)/32), dim3(32, 8)>>>(Wo, wohf, HQ*D, E);

    // 5) fused Q|K projection + RoPE + split epilogue
    mma_gemm_qk_kernel<<<dim3(2560/128, M/128), 256, GEMM_SMEM>>>(
        xhi, xlo, wqkhi, wqklo, rcos, rsin);

    // 6) V projection (fp16 single term), writes g_vh directly
    mma_gemm1_kernel<true><<<dim3(512/128, M/128), 256, GEMM1_SMEM>>>(
        M, 512, E, xh, wvh, (void*)vhp);

    // 7) tensor-core flash attention
    flash_mma_kernel<<<dim3(S / 128, HQ, B), 256, FLASH_SMEM>>>();

    // 8) O-projection (fp16, single term)
    mma_gemm1_kernel<false><<<dim3(E/128, M/128), 256, GEMM1_SMEM>>>(
        M, E, HQ*D, ofp, wohf, (void*)out);
}

// round 13
// speedup vs baseline: 1.0719x; 1.0719x over previous
#include <cuda_runtime.h>
#include <cuda_bf16.h>
#include <cuda_fp16.h>
#include <cstdint>

// Problem constants
#define B 2
#define S 2048
#define E 2048
#define HQ 32
#define HK 8
#define D 64

// ---------------------------------------------------------------------------
// Scratch (device globals)
// ---------------------------------------------------------------------------
__device__ float g_qk[(size_t)B * S * 2560];             // fused Q|K fp32

__device__ __nv_bfloat16 g_xhi[(size_t)B * S * E];
__device__ __nv_bfloat16 g_xlo[(size_t)B * S * E];
__device__ __half        g_xh[(size_t)B * S * E];        // x fp16 (for v-proj)
__device__ __nv_bfloat16 g_wqkhi[(size_t)2560 * E];      // [N=2560, K=2048]
__device__ __nv_bfloat16 g_wqklo[(size_t)2560 * E];
__device__ __half        g_wvh[(size_t)512 * E];         // Wv^T fp16
__device__ __half        g_wohf[(size_t)E * HQ * D];     // Wo^T fp16

__device__ __nv_bfloat16 g_qhi[(size_t)B * S * HQ * D]; // post-RoPE bf16
__device__ __nv_bfloat16 g_qlo[(size_t)B * S * HQ * D];
__device__ __nv_bfloat16 g_khi[(size_t)B * S * HK * D];
__device__ __nv_bfloat16 g_klo[(size_t)B * S * HK * D];
__device__ __half        g_vh[(size_t)B * S * HK * D];  // v fp16 (from GEMM)
__device__ __half        g_of[(size_t)B * S * HQ * D];  // attention out, fp16

// ---------------------------------------------------------------------------
// PTX helpers (base-target safe)
// ---------------------------------------------------------------------------
__device__ __forceinline__ uint32_t smem_u32(const void* p) {
    uint32_t a;
    asm("{ .reg .u64 t; cvta.to.shared.u64 t, %1; cvt.u32.u64 %0, t; }"
        : "=r"(a) : "l"(p));
    return a;
}
__device__ __forceinline__ void cp16(uint32_t dst, const void* src) {
    asm volatile("cp.async.cg.shared.global [%0], [%1], 16;"
                 :: "r"(dst), "l"(src) : "memory");
}
__device__ __forceinline__ void cp_commit() {
    asm volatile("cp.async.commit_group;" ::: "memory");
}
template <int N>
__device__ __forceinline__ void cp_wait() {
    asm volatile("cp.async.wait_group %0;" :: "n"(N) : "memory");
}
__device__ __forceinline__ void ldm4(uint32_t* r, uint32_t addr) {
    asm volatile("ldmatrix.sync.aligned.m8n8.x4.shared.b16 {%0,%1,%2,%3}, [%4];"
                 : "=r"(r[0]), "=r"(r[1]), "=r"(r[2]), "=r"(r[3]) : "r"(addr));
}
__device__ __forceinline__ void ldm4t(uint32_t* r, uint32_t addr) {
    asm volatile("ldmatrix.sync.aligned.m8n8.x4.trans.shared.b16 {%0,%1,%2,%3}, [%4];"
                 : "=r"(r[0]), "=r"(r[1]), "=r"(r[2]), "=r"(r[3]) : "r"(addr));
}
__device__ __forceinline__ void mma_bf16(float* c, const uint32_t* a,
                                         const uint32_t* b) {
    asm volatile(
        "mma.sync.aligned.m16n8k16.row.col.f32.bf16.bf16.f32 "
        "{%0,%1,%2,%3}, {%4,%5,%6,%7}, {%8,%9}, {%0,%1,%2,%3};"
        : "+f"(c[0]), "+f"(c[1]), "+f"(c[2]), "+f"(c[3])
        : "r"(a[0]), "r"(a[1]), "r"(a[2]), "r"(a[3]), "r"(b[0]), "r"(b[1]));
}
__device__ __forceinline__ void mma_f16(float* c, const uint32_t* a,
                                        const uint32_t* b) {
    asm volatile(
        "mma.sync.aligned.m16n8k16.row.col.f32.f16.f16.f32 "
        "{%0,%1,%2,%3}, {%4,%5,%6,%7}, {%8,%9}, {%0,%1,%2,%3};"
        : "+f"(c[0]), "+f"(c[1]), "+f"(c[2]), "+f"(c[3])
        : "r"(a[0]), "r"(a[1]), "r"(a[2]), "r"(a[3]), "r"(b[0]), "r"(b[1]));
}
__device__ __forceinline__ uint32_t packbf(__nv_bfloat16 a, __nv_bfloat16 b) {
    __nv_bfloat162 t = __halves2bfloat162(a, b);
    return *(uint32_t*)&t;
}
__device__ __forceinline__ uint32_t packh(float x, float y) {
    __half2 t = __floats2half2_rn(x, y);
    return *(uint32_t*)&t;
}
__device__ __forceinline__ void split2(float x, float y,
                                       uint32_t& hi, uint32_t& lo) {
    __nv_bfloat16 hx = __float2bfloat16(x), hy = __float2bfloat16(y);
    __nv_bfloat16 lx = __float2bfloat16(x - __bfloat162float(hx));
    __nv_bfloat16 ly = __float2bfloat16(y - __bfloat162float(hy));
    hi = packbf(hx, hy);
    lo = packbf(lx, ly);
}
__device__ __forceinline__ void splitf(float x, __nv_bfloat16& h, __nv_bfloat16& l) {
    h = __float2bfloat16(x);
    l = __float2bfloat16(x - __bfloat162float(h));
}

// ---------------------------------------------------------------------------
// Split fp32 -> bf16 hi/lo + fp16 single
// ---------------------------------------------------------------------------
__global__ void split3_kernel(const float* __restrict__ src,
                              __nv_bfloat16* __restrict__ hi,
                              __nv_bfloat16* __restrict__ lo,
                              __half* __restrict__ hf, int n4)
{
    int i = blockIdx.x * blockDim.x + threadIdx.x;
    if (i >= n4) return;
    float4 v = ((const float4*)src)[i];
    uint32_t h0, l0, h1, l1;
    split2(v.x, v.y, h0, l0);
    split2(v.z, v.w, h1, l1);
    ((uint32_t*)hi)[2*i]   = h0;
    ((uint32_t*)hi)[2*i+1] = h1;
    ((uint32_t*)lo)[2*i]   = l0;
    ((uint32_t*)lo)[2*i+1] = l1;
    ((uint32_t*)hf)[2*i]   = packh(v.x, v.y);
    ((uint32_t*)hf)[2*i+1] = packh(v.z, v.w);
}

// ---------------------------------------------------------------------------
// Transpose W[K,N] -> Wt[N,K], bf16 hi/lo
// ---------------------------------------------------------------------------
__global__ __launch_bounds__(256) void transpose_split_kernel(
    const float* __restrict__ W,
    __nv_bfloat16* __restrict__ hiT,
    __nv_bfloat16* __restrict__ loT, int K, int N)
{
    __shared__ float t[32][33];
    int n0 = blockIdx.x * 32, k0 = blockIdx.y * 32;
    int tx = threadIdx.x, ty = threadIdx.y;
#pragma unroll
    for (int r = 0; r < 4; r++)
        t[ty + r*8][tx] = W[(size_t)(k0 + ty + r*8) * N + n0 + tx];
    __syncthreads();
#pragma unroll
    for (int r = 0; r < 4; r++) {
        int n = n0 + ty + r*8;
        float v = t[tx][ty + r*8];
        __nv_bfloat16 h = __float2bfloat16(v);
        hiT[(size_t)n * K + k0 + tx] = h;
        loT[(size_t)n * K + k0 + tx] = __float2bfloat16(v - __bfloat162float(h));
    }
}

// Transpose W[K,N] -> Wt[N,K], single fp16
__global__ __launch_bounds__(256) void transpose_h_kernel(
    const float* __restrict__ W,
    __half* __restrict__ hT, int K, int N)
{
    __shared__ float t[32][33];
    int n0 = blockIdx.x * 32, k0 = blockIdx.y * 32;
    int tx = threadIdx.x, ty = threadIdx.y;
#pragma unroll
    for (int r = 0; r < 4; r++)
        t[ty + r*8][tx] = W[(size_t)(k0 + ty + r*8) * N + n0 + tx];
    __syncthreads();
#pragma unroll
    for (int r = 0; r < 4; r++) {
        int n = n0 + ty + r*8;
        hT[(size_t)n * K + k0 + tx] = __float2half_rn(t[tx][ty + r*8]);
    }
}

// ---------------------------------------------------------------------------
// Combined projection kernel: blockIdx.x < 20 -> QK bf16 3-term tile
// (N=2560, fp32 out to g_qk); else -> V fp16 1-term tile (N=512, fp16 out
// to g_vh). Packs V's 128 CTAs into the QK launch's tail wave. 2 CTAs/SM.
// ---------------------------------------------------------------------------
#define TSTRIDE 80
#define TILE_BYTES (128 * TSTRIDE)
#define STAGE_BYTES (4 * TILE_BYTES)
#define GEMM_SMEM (2 * STAGE_BYTES)

__device__ __forceinline__ void load_stage(
    uint32_t base, int tid,
    const __nv_bfloat16* Ah, const __nv_bfloat16* Al,
    const __nv_bfloat16* Bh, const __nv_bfloat16* Bl,
    int K, int k0)
{
    int ch = tid & 3;
    int rhalf = tid >> 2;
#pragma unroll
    for (int i = 0; i < 8; i++) {
        int tile = i >> 1;
        int row = (i & 1) * 64 + rhalf;
        uint32_t dst = base + tile * TILE_BYTES + row * TSTRIDE + ch * 16;
        const __nv_bfloat16* src =
            (tile == 0) ? Ah : (tile == 1) ? Al : (tile == 2) ? Bh : Bl;
        cp16(dst, src + (size_t)row * K + k0 + ch * 8);
    }
}

#define STAGE1_BYTES (2 * TILE_BYTES)

__device__ __forceinline__ void load_stage1(
    uint32_t base, int tid,
    const __half* A, const __half* Bh, int K, int k0)
{
    int ch = tid & 3;
    int rhalf = tid >> 2;
#pragma unroll
    for (int i = 0; i < 4; i++) {
        int tile = i >> 1;
        int row = (i & 1) * 64 + rhalf;
        uint32_t dst = base + tile * TILE_BYTES + row * TSTRIDE + ch * 16;
        const __half* src = (tile == 0) ? A : Bh;
        cp16(dst, src + (size_t)row * K + k0 + ch * 8);
    }
}

__global__ __launch_bounds__(256, 2) void qkv_proj_kernel()
{
    const int K = E;
    extern __shared__ char smem[];
    uint32_t sb = smem_u32(smem);
    int tid = threadIdx.x;
    int lane = tid & 31, wid = tid >> 5;
    int wm = wid & 1, wn = wid >> 1;
    int bm = blockIdx.y * 128;

    float acc[4][4][4];
#pragma unroll
    for (int i = 0; i < 4; i++)
#pragma unroll
        for (int j = 0; j < 4; j++)
#pragma unroll
            for (int r = 0; r < 4; r++) acc[i][j][r] = 0.f;

    uint32_t aoff = (uint32_t)((wm * 64 + (lane & 15)) * TSTRIDE + (lane >> 4) * 16);
    uint32_t boff = (uint32_t)((wn * 32 + ((lane >> 4) * 8) + (lane & 7)) * TSTRIDE
                               + ((lane >> 3) & 1) * 16);
    const int nch = K >> 5;

    if (blockIdx.x < 20) {
        // ---------------- QK path: bf16 3-term, fp32 out ----------------
        int bn = blockIdx.x * 128;
        const __nv_bfloat16* Ah = g_xhi + (size_t)bm * K;
        const __nv_bfloat16* Al = g_xlo + (size_t)bm * K;
        const __nv_bfloat16* Bh = g_wqkhi + (size_t)bn * K;
        const __nv_bfloat16* Bl = g_wqklo + (size_t)bn * K;

        load_stage(sb, tid, Ah, Al, Bh, Bl, K, 0);
        cp_commit();

        for (int ch = 0; ch < nch; ch++) {
            if (ch + 1 < nch) {
                load_stage(sb + ((ch + 1) & 1) * STAGE_BYTES, tid,
                           Ah, Al, Bh, Bl, K, (ch + 1) << 5);
                cp_commit();
                cp_wait<1>();
            } else {
                cp_wait<0>();
            }
            __syncthreads();

            uint32_t st = sb + (ch & 1) * STAGE_BYTES;
            uint32_t sAhi = st;
            uint32_t sAlo = st + TILE_BYTES;
            uint32_t sBhi = st + 2 * TILE_BYTES;
            uint32_t sBlo = st + 3 * TILE_BYTES;

#pragma unroll
            for (int ks = 0; ks < 2; ks++) {
                uint32_t kb = ks * 32;
                uint32_t bh[8], bl[8], a[16];
                ldm4(bh + 0, sBhi + boff + kb);
                ldm4(bh + 4, sBhi + boff + 16 * TSTRIDE + kb);
                ldm4(bl + 0, sBlo + boff + kb);
                ldm4(bl + 4, sBlo + boff + 16 * TSTRIDE + kb);
#pragma unroll
                for (int mt = 0; mt < 4; mt++)
                    ldm4(a + 4 * mt, sAhi + aoff + mt * 16 * TSTRIDE + kb);
#pragma unroll
                for (int mt = 0; mt < 4; mt++)
#pragma unroll
                    for (int nt = 0; nt < 4; nt++)
                        mma_bf16(acc[mt][nt], a + 4 * mt, bh + 2 * nt);
#pragma unroll
                for (int mt = 0; mt < 4; mt++)
#pragma unroll
                    for (int nt = 0; nt < 4; nt++)
                        mma_bf16(acc[mt][nt], a + 4 * mt, bl + 2 * nt);
#pragma unroll
                for (int mt = 0; mt < 4; mt++)
                    ldm4(a + 4 * mt, sAlo + aoff + mt * 16 * TSTRIDE + kb);
#pragma unroll
                for (int mt = 0; mt < 4; mt++)
#pragma unroll
                    for (int nt = 0; nt < 4; nt++)
                        mma_bf16(acc[mt][nt], a + 4 * mt, bh + 2 * nt);
            }
            __syncthreads();
        }

        int r0 = bm + wm * 64 + (lane >> 2);
        int c0 = bn + wn * 32 + (lane & 3) * 2;
#pragma unroll
        for (int mt = 0; mt < 4; mt++) {
#pragma unroll
            for (int nt = 0; nt < 4; nt++) {
                int row = r0 + mt * 16;
                int col = c0 + nt * 8;
                *(float2*)&g_qk[(size_t)row * 2560 + col] =
                    make_float2(acc[mt][nt][0], acc[mt][nt][1]);
                *(float2*)&g_qk[(size_t)(row + 8) * 2560 + col] =
                    make_float2(acc[mt][nt][2], acc[mt][nt][3]);
            }
        }
    } else {
        // ---------------- V path: fp16 1-term, fp16 out ----------------
        int bn = (blockIdx.x - 20) * 128;
        const __half* Ap = g_xh + (size_t)bm * K;
        const __half* Bh = g_wvh + (size_t)bn * K;

        load_stage1(sb, tid, Ap, Bh, K, 0);
        cp_commit();

        for (int ch = 0; ch < nch; ch++) {
            if (ch + 1 < nch) {
                load_stage1(sb + ((ch + 1) & 1) * STAGE1_BYTES, tid,
                            Ap, Bh, K, (ch + 1) << 5);
                cp_commit();
                cp_wait<1>();
            } else {
                cp_wait<0>();
            }
            __syncthreads();

            uint32_t st = sb + (ch & 1) * STAGE1_BYTES;
            uint32_t sA = st;
            uint32_t sB = st + TILE_BYTES;

#pragma unroll
            for (int ks = 0; ks < 2; ks++) {
                uint32_t kb = ks * 32;
                uint32_t bh[8], a[16];
                ldm4(bh + 0, sB + boff + kb);
                ldm4(bh + 4, sB + boff + 16 * TSTRIDE + kb);
#pragma unroll
                for (int mt = 0; mt < 4; mt++)
                    ldm4(a + 4 * mt, sA + aoff + mt * 16 * TSTRIDE + kb);
#pragma unroll
                for (int mt = 0; mt < 4; mt++)
#pragma unroll
                    for (int nt = 0; nt < 4; nt++)
                        mma_f16(acc[mt][nt], a + 4 * mt, bh + 2 * nt);
            }
            __syncthreads();
        }

        int r0 = bm + wm * 64 + (lane >> 2);
        int c0 = bn + wn * 32 + (lane & 3) * 2;
#pragma unroll
        for (int mt = 0; mt < 4; mt++) {
#pragma unroll
            for (int nt = 0; nt < 4; nt++) {
                int row = r0 + mt * 16;
                int col = c0 + nt * 8;
                *(uint32_t*)&g_vh[(size_t)row * 512 + col] =
                    packh(acc[mt][nt][0], acc[mt][nt][1]);
                *(uint32_t*)&g_vh[(size_t)(row + 8) * 512 + col] =
                    packh(acc[mt][nt][2], acc[mt][nt][3]);
            }
        }
    }
}

// ---------------------------------------------------------------------------
// fp16 single-term GEMM (O-projection) — 2 CTAs/SM
// ---------------------------------------------------------------------------
#define GEMM1_SMEM (2 * STAGE1_BYTES)

__global__ __launch_bounds__(256, 2) void mma_gemm1_kernel(
    int M, int N, int K,
    const __half* __restrict__ A,
    const __half* __restrict__ Bhi,
    float* __restrict__ C)
{
    extern __shared__ char smem[];
    uint32_t sb = smem_u32(smem);
    int tid = threadIdx.x;
    int lane = tid & 31, wid = tid >> 5;
    int wm = wid & 1, wn = wid >> 1;
    int bm = blockIdx.y * 128, bn = blockIdx.x * 128;

    const __half* Ap = A + (size_t)bm * K;
    const __half* Bh = Bhi + (size_t)bn * K;

    float acc[4][4][4];
#pragma unroll
    for (int i = 0; i < 4; i++)
#pragma unroll
        for (int j = 0; j < 4; j++)
#pragma unroll
            for (int r = 0; r < 4; r++) acc[i][j][r] = 0.f;

    uint32_t aoff = (uint32_t)((wm * 64 + (lane & 15)) * TSTRIDE + (lane >> 4) * 16);
    uint32_t boff = (uint32_t)((wn * 32 + ((lane >> 4) * 8) + (lane & 7)) * TSTRIDE
                               + ((lane >> 3) & 1) * 16);

    const int nch = K >> 5;
    load_stage1(sb, tid, Ap, Bh, K, 0);
    cp_commit();

    for (int ch = 0; ch < nch; ch++) {
        if (ch + 1 < nch) {
            load_stage1(sb + ((ch + 1) & 1) * STAGE1_BYTES, tid,
                        Ap, Bh, K, (ch + 1) << 5);
            cp_commit();
            cp_wait<1>();
        } else {
            cp_wait<0>();
        }
        __syncthreads();

        uint32_t st = sb + (ch & 1) * STAGE1_BYTES;
        uint32_t sA = st;
        uint32_t sB = st + TILE_BYTES;

#pragma unroll
        for (int ks = 0; ks < 2; ks++) {
            uint32_t kb = ks * 32;
            uint32_t bh[8], a[16];
            ldm4(bh + 0, sB + boff + kb);
            ldm4(bh + 4, sB + boff + 16 * TSTRIDE + kb);
#pragma unroll
            for (int mt = 0; mt < 4; mt++)
                ldm4(a + 4 * mt, sA + aoff + mt * 16 * TSTRIDE + kb);
#pragma unroll
            for (int mt = 0; mt < 4; mt++)
#pragma unroll
                for (int nt = 0; nt < 4; nt++)
                    mma_f16(acc[mt][nt], a + 4 * mt, bh + 2 * nt);
        }
        __syncthreads();
    }

    int r0 = bm + wm * 64 + (lane >> 2);
    int c0 = bn + wn * 32 + (lane & 3) * 2;
#pragma unroll
    for (int mt = 0; mt < 4; mt++) {
#pragma unroll
        for (int nt = 0; nt < 4; nt++) {
            int row = r0 + mt * 16;
            int col = c0 + nt * 8;
            *(float2*)&C[(size_t)row * N + col] =
                make_float2(acc[mt][nt][0], acc[mt][nt][1]);
            *(float2*)&C[(size_t)(row + 8) * N + col] =
                make_float2(acc[mt][nt][2], acc[mt][nt][3]);
        }
    }
}

// ---------------------------------------------------------------------------
// Fused RoPE + bf16 hi/lo split over the fused q|k buffer (width 2560).
// ---------------------------------------------------------------------------
#define PAIRS_PER_ROW 1280   // 1024 q + 256 k

__global__ void rope_split_kernel(const float* __restrict__ qk,
                                  const float* __restrict__ cs,
                                  const float* __restrict__ sn)
{
    int idx = blockIdx.x * blockDim.x + threadIdx.x;
    if (idx >= B * S * PAIRS_PER_ROW) return;
    int row = idx / PAIRS_PER_ROW;
    int pid = idx - row * PAIRS_PER_ROW;
    int s = row & (S - 1);

    if (pid < 1024) {                 // q
        int h = pid >> 5, d = pid & 31;
        const float* base = qk + (size_t)row * 2560 + h * 64;
        float v1 = base[d], v2 = base[d + 32];
        float c = cs[s * 32 + d], si = sn[s * 32 + d];
        float r1 = v1 * c - v2 * si;
        float r2 = v2 * c + v1 * si;
        __nv_bfloat16 h1, l1, h2, l2;
        splitf(r1, h1, l1); splitf(r2, h2, l2);
        size_t o = ((size_t)row * HQ + h) * 64 + d;
        g_qhi[o] = h1; g_qlo[o] = l1;
        g_qhi[o + 32] = h2; g_qlo[o + 32] = l2;
    } else {                          // k
        int kp = pid - 1024;
        int h = kp >> 5, d = kp & 31;
        const float* base = qk + (size_t)row * 2560 + 2048 + h * 64;
        float v1 = base[d], v2 = base[d + 32];
        float c = cs[s * 32 + d], si = sn[s * 32 + d];
        float r1 = v1 * c - v2 * si;
        float r2 = v2 * c + v1 * si;
        __nv_bfloat16 h1, l1, h2, l2;
        splitf(r1, h1, l1); splitf(r2, h2, l2);
        size_t o = ((size_t)row * HK + h) * 64 + d;
        g_khi[o] = h1; g_klo[o] = l1;
        g_khi[o + 32] = h2; g_klo[o + 32] = l2;
    }
}

// ---------------------------------------------------------------------------
// Tensor-core flash attention — 2 CTAs/SM (R11-verified).
// QK: bf16 3-term. PV: p fp16 x v fp16 (1 term). fp16 out.
// ---------------------------------------------------------------------------
#define FSTRIDE 144
#define FTILE (64 * FSTRIDE)
#define FSTAGE (3 * FTILE)              // khi, klo, vh
#define QTILE (128 * FSTRIDE)
#define FLASH_SMEM (2 * FSTAGE)         // 55296

__global__ __launch_bounds__(256, 2) void flash_mma_kernel()
{
    extern __shared__ char smem[];
    uint32_t sb = smem_u32(smem);
    int tid = threadIdx.x;
    int lane = tid & 31, wq = tid >> 5;
    int qbase = blockIdx.x * 128;
    int h = blockIdx.y, b = blockIdx.z;
    int kh = h >> 2;

    // ---- stage Q hi/lo, build fragments ----
#pragma unroll
    for (int i = 0; i < 8; i++) {
        int lin = i * 256 + tid;
        int arr = lin >> 10;
        int rem = lin & 1023;
        int row = rem >> 3;
        int seg = rem & 7;
        const __nv_bfloat16* src = arr ? g_qlo : g_qhi;
        cp16(sb + arr * QTILE + row * FSTRIDE + seg * 16,
             src + ((size_t)(b * S + qbase + row) * HQ + h) * 64 + seg * 8);
    }
    cp_commit();
    cp_wait<0>();
    __syncthreads();

    uint32_t qhi[4][4], qlo[4][4];
    {
        uint32_t qoff = (uint32_t)((wq * 16 + (lane & 15)) * FSTRIDE + (lane >> 4) * 16);
#pragma unroll
        for (int ks = 0; ks < 4; ks++) {
            ldm4(qhi[ks], sb + qoff + ks * 32);
            ldm4(qlo[ks], sb + QTILE + qoff + ks * 32);
        }
    }
    __syncthreads();

    // ---- kv staging (3 arrays: khi, klo bf16; vh fp16) ----
    const uint8_t* srcs[3];
    srcs[0] = (const uint8_t*)(g_khi + ((size_t)b * S * HK + kh) * D);
    srcs[1] = (const uint8_t*)(g_klo + ((size_t)b * S * HK + kh) * D);
    srcs[2] = (const uint8_t*)(g_vh + ((size_t)b * S * HK + kh) * D);

    auto prefetch = [&](int t) {
        uint32_t base = sb + (t & 1) * FSTAGE;
        int key0 = t * 64;
#pragma unroll
        for (int i = 0; i < 6; i++) {
            int lin = i * 256 + tid;
            int arr = lin >> 9;
            int rem = lin & 511;
            int row = rem >> 3;
            int seg = rem & 7;
            cp16(base + arr * FTILE + row * FSTRIDE + seg * 16,
                 srcs[arr] + (size_t)(key0 + row) * (HK * D * 2) + seg * 16);
        }
        cp_commit();
    };

    uint32_t boff = (uint32_t)(((lane >> 4) * 8 + (lane & 7)) * FSTRIDE
                               + ((lane >> 3) & 1) * 16);
    uint32_t voff = (uint32_t)((lane & 15) * FSTRIDE + (lane >> 4) * 16);

    float o_[8][4];
#pragma unroll
    for (int nt = 0; nt < 8; nt++)
#pragma unroll
        for (int r = 0; r < 4; r++) o_[nt][r] = 0.f;
    float m0 = -1e30f, m1 = -1e30f, l0 = 0.f, l1 = 0.f;

    prefetch(0);

    const int NT = S / 64;
    for (int t = 0; t < NT; t++) {
        if (t + 1 < NT) { prefetch(t + 1); cp_wait<1>(); }
        else           { cp_wait<0>(); }
        __syncthreads();

        uint32_t st = sb + (t & 1) * FSTAGE;
        uint32_t sKhi = st, sKlo = st + FTILE;
        uint32_t sVh = st + 2 * FTILE;

        float s[8][4];
#pragma unroll
        for (int nt = 0; nt < 8; nt++)
#pragma unroll
            for (int r = 0; r < 4; r++) s[nt][r] = 0.f;

        // QK, processed in two 4-nt halves (reduced b-frag live range)
#pragma unroll
        for (int ks = 0; ks < 4; ks++) {
            uint32_t kb = ks * 32;
#pragma unroll
            for (int hf = 0; hf < 2; hf++) {
                uint32_t rb = hf * 32 * FSTRIDE;
                uint32_t bh[8], bl[8];
                ldm4(bh + 0, sKhi + boff + rb + kb);
                ldm4(bh + 4, sKhi + boff + rb + 16 * FSTRIDE + kb);
                ldm4(bl + 0, sKlo + boff + rb + kb);
                ldm4(bl + 4, sKlo + boff + rb + 16 * FSTRIDE + kb);
#pragma unroll
                for (int j = 0; j < 4; j++) {
                    int nt = hf * 4 + j;
                    mma_bf16(s[nt], qhi[ks], bh + 2*j);
                    mma_bf16(s[nt], qhi[ks], bl + 2*j);
                    mma_bf16(s[nt], qlo[ks], bh + 2*j);
                }
            }
        }

        float tmax0 = -1e30f, tmax1 = -1e30f;
#pragma unroll
        for (int nt = 0; nt < 8; nt++) {
            tmax0 = fmaxf(tmax0, fmaxf(s[nt][0], s[nt][1]));
            tmax1 = fmaxf(tmax1, fmaxf(s[nt][2], s[nt][3]));
        }
        tmax0 = fmaxf(tmax0, __shfl_xor_sync(0xffffffffu, tmax0, 1));
        tmax0 = fmaxf(tmax0, __shfl_xor_sync(0xffffffffu, tmax0, 2));
        tmax1 = fmaxf(tmax1, __shfl_xor_sync(0xffffffffu, tmax1, 1));
        tmax1 = fmaxf(tmax1, __shfl_xor_sync(0xffffffffu, tmax1, 2));
        float nm0 = fmaxf(m0, tmax0), nm1 = fmaxf(m1, tmax1);
        float a0 = __expf(m0 - nm0), a1 = __expf(m1 - nm1);
        m0 = nm0; m1 = nm1;
        float ps0 = 0.f, ps1 = 0.f;
#pragma unroll
        for (int nt = 0; nt < 8; nt++) {
            s[nt][0] = __expf(s[nt][0] - m0);
            s[nt][1] = __expf(s[nt][1] - m0);
            s[nt][2] = __expf(s[nt][2] - m1);
            s[nt][3] = __expf(s[nt][3] - m1);
            ps0 += s[nt][0] + s[nt][1];
            ps1 += s[nt][2] + s[nt][3];
        }
        l0 = l0 * a0 + ps0;
        l1 = l1 * a1 + ps1;
#pragma unroll
        for (int nt = 0; nt < 8; nt++) {
            o_[nt][0] *= a0; o_[nt][1] *= a0;
            o_[nt][2] *= a1; o_[nt][3] *= a1;
        }

        // ---- PV: p fp16 x v fp16, single term ----
#pragma unroll
        for (int ks = 0; ks < 4; ks++) {
            uint32_t ph[4];
            ph[0] = packh(s[2*ks][0],   s[2*ks][1]);
            ph[1] = packh(s[2*ks][2],   s[2*ks][3]);
            ph[2] = packh(s[2*ks+1][0], s[2*ks+1][1]);
            ph[3] = packh(s[2*ks+1][2], s[2*ks+1][3]);
            uint32_t rbase = ks * 16 * FSTRIDE;
#pragma unroll
            for (int n2 = 0; n2 < 4; n2++) {
                uint32_t vh[4];
                ldm4t(vh, sVh + voff + rbase + n2 * 32);
                mma_f16(o_[2*n2],     ph, vh + 0);
                mma_f16(o_[2*n2 + 1], ph, vh + 2);
            }
        }
        __syncthreads();
    }

    // ---- finalize: write single fp16 ----
    l0 += __shfl_xor_sync(0xffffffffu, l0, 1);
    l0 += __shfl_xor_sync(0xffffffffu, l0, 2);
    l1 += __shfl_xor_sync(0xffffffffu, l1, 1);
    l1 += __shfl_xor_sync(0xffffffffu, l1, 2);
    float inv0 = 1.f / l0, inv1 = 1.f / l1;

    int r = qbase + wq * 16 + (lane >> 2);
    int c = (lane & 3) * 2;
    size_t ob0 = ((size_t)(b * S + r) * HQ + h) * D;
    size_t ob1 = ((size_t)(b * S + r + 8) * HQ + h) * D;
#pragma unroll
    for (int nt = 0; nt < 8; nt++) {
        *(uint32_t*)(g_of + ob0 + nt * 8 + c) =
            packh(o_[nt][0] * inv0, o_[nt][1] * inv0);
        *(uint32_t*)(g_of + ob1 + nt * 8 + c) =
            packh(o_[nt][2] * inv1, o_[nt][3] * inv1);
    }
}

// ---------------------------------------------------------------------------
// Launch
// ---------------------------------------------------------------------------
extern "C" void kernel_launch(void* const* d_in, const int* in_sizes, int n_in,
                              void* d_out, int out_size)
{
    const float* x    = (const float*)d_in[0];
    const float* rcos = (const float*)d_in[1];
    const float* rsin = (const float*)d_in[2];
    const float* Wq   = (const float*)d_in[4];
    const float* Wk   = (const float*)d_in[5];
    const float* Wv   = (const float*)d_in[6];
    const float* Wo   = (const float*)d_in[7];
    float* out = (float*)d_out;

    float* qkp;
    cudaGetSymbolAddress((void**)&qkp, g_qk);
    __nv_bfloat16 *xhi, *xlo, *wqkhi, *wqklo;
    __half *xh, *wvh, *wohf, *ofp;
    cudaGetSymbolAddress((void**)&xhi, g_xhi);
    cudaGetSymbolAddress((void**)&xlo, g_xlo);
    cudaGetSymbolAddress((void**)&xh, g_xh);
    cudaGetSymbolAddress((void**)&wqkhi, g_wqkhi);
    cudaGetSymbolAddress((void**)&wqklo, g_wqklo);
    cudaGetSymbolAddress((void**)&wvh, g_wvh);
    cudaGetSymbolAddress((void**)&wohf, g_wohf);
    cudaGetSymbolAddress((void**)&ofp, g_of);

    cudaFuncSetAttribute(qkv_proj_kernel,
                         cudaFuncAttributeMaxDynamicSharedMemorySize, GEMM_SMEM);
    cudaFuncSetAttribute(mma_gemm1_kernel,
                         cudaFuncAttributeMaxDynamicSharedMemorySize, GEMM1_SMEM);
    cudaFuncSetAttribute(flash_mma_kernel,
                         cudaFuncAttributeMaxDynamicSharedMemorySize, FLASH_SMEM);

    const int M = B * S;  // 4096

    // 0) split x -> bf16 hi/lo + fp16
    {
        int n4 = M * E / 4;
        split3_kernel<<<(n4 + 255) / 256, 256>>>(x, xhi, xlo, xh, n4);
    }
    // 1-2) transpose+split Wq/Wk (bf16) into concatenated [2560, 2048]
    transpose_split_kernel<<<dim3((HQ*D)/32, E/32), dim3(32, 8)>>>(
        Wq, wqkhi, wqklo, E, HQ*D);
    transpose_split_kernel<<<dim3((HK*D)/32, E/32), dim3(32, 8)>>>(
        Wk, wqkhi + (size_t)2048 * E, wqklo + (size_t)2048 * E, E, HK*D);
    // 3) transpose Wv (fp16), 4) transpose Wo (fp16)
    transpose_h_kernel<<<dim3((HK*D)/32, E/32), dim3(32, 8)>>>(Wv, wvh, E, HK*D);
    transpose_h_kernel<<<dim3(E/32, (HQ*D)/32), dim3(32, 8)>>>(Wo, wohf, HQ*D, E);

    // 5) combined Q|K (bf16 3-term) + V (fp16 1-term) projection, one launch
    qkv_proj_kernel<<<dim3(24, M/128), 256, GEMM_SMEM>>>();

    // 6) fused RoPE + split (q,k only)
    {
        int tot = B * S * PAIRS_PER_ROW;
        rope_split_kernel<<<(tot + 255) / 256, 256>>>(qkp, rcos, rsin);
    }

    // 7) tensor-core flash attention
    flash_mma_kernel<<<dim3(S / 128, HQ, B), 256, FLASH_SMEM>>>();

    // 8) O-projection (fp16, single term)
    mma_gemm1_kernel<<<dim3(E/128, M/128), 256, GEMM1_SMEM>>>(
        M, E, HQ*D, ofp, wohf, out);
}

// round 16
// speedup vs baseline: 1.0792x; 1.0068x over previous
#include <cuda_runtime.h>
#include <cuda_bf16.h>
#include <cuda_fp16.h>
#include <cstdint>

// Problem constants
#define B 2
#define S 2048
#define E 2048
#define HQ 32
#define HK 8
#define D 64

// ---------------------------------------------------------------------------
// Scratch (device globals)
// ---------------------------------------------------------------------------
__device__ float g_qk[(size_t)B * S * 2560];             // fused Q|K fp32

__device__ __nv_bfloat16 g_xhi[(size_t)B * S * E];
__device__ __nv_bfloat16 g_xlo[(size_t)B * S * E];
__device__ __half        g_xh[(size_t)B * S * E];        // x fp16 (for v-proj)
__device__ __nv_bfloat16 g_wqkhi[(size_t)2560 * E];      // [N=2560, K=2048]
__device__ __nv_bfloat16 g_wqklo[(size_t)2560 * E];
__device__ __half        g_wvh[(size_t)512 * E];         // Wv^T fp16
__device__ __half        g_wohf[(size_t)E * HQ * D];     // Wo^T fp16

__device__ __nv_bfloat16 g_qhi[(size_t)B * S * HQ * D]; // post-RoPE bf16
__device__ __nv_bfloat16 g_qlo[(size_t)B * S * HQ * D];
__device__ __nv_bfloat16 g_khi[(size_t)B * S * HK * D];
__device__ __nv_bfloat16 g_klo[(size_t)B * S * HK * D];
__device__ __half        g_vh[(size_t)B * S * HK * D];  // v fp16 (from GEMM)
__device__ __half        g_of[(size_t)B * S * HQ * D];  // attention out, fp16

// ---------------------------------------------------------------------------
// PTX helpers (base-target safe)
// ---------------------------------------------------------------------------
__device__ __forceinline__ uint32_t smem_u32(const void* p) {
    uint32_t a;
    asm("{ .reg .u64 t; cvta.to.shared.u64 t, %1; cvt.u32.u64 %0, t; }"
        : "=r"(a) : "l"(p));
    return a;
}
__device__ __forceinline__ void cp16(uint32_t dst, const void* src) {
    asm volatile("cp.async.cg.shared.global [%0], [%1], 16;"
                 :: "r"(dst), "l"(src) : "memory");
}
__device__ __forceinline__ void cp_commit() {
    asm volatile("cp.async.commit_group;" ::: "memory");
}
template <int N>
__device__ __forceinline__ void cp_wait() {
    asm volatile("cp.async.wait_group %0;" :: "n"(N) : "memory");
}
__device__ __forceinline__ void ldm4(uint32_t* r, uint32_t addr) {
    asm volatile("ldmatrix.sync.aligned.m8n8.x4.shared.b16 {%0,%1,%2,%3}, [%4];"
                 : "=r"(r[0]), "=r"(r[1]), "=r"(r[2]), "=r"(r[3]) : "r"(addr));
}
__device__ __forceinline__ void ldm4t(uint32_t* r, uint32_t addr) {
    asm volatile("ldmatrix.sync.aligned.m8n8.x4.trans.shared.b16 {%0,%1,%2,%3}, [%4];"
                 : "=r"(r[0]), "=r"(r[1]), "=r"(r[2]), "=r"(r[3]) : "r"(addr));
}
__device__ __forceinline__ void mma_bf16(float* c, const uint32_t* a,
                                         const uint32_t* b) {
    asm volatile(
        "mma.sync.aligned.m16n8k16.row.col.f32.bf16.bf16.f32 "
        "{%0,%1,%2,%3}, {%4,%5,%6,%7}, {%8,%9}, {%0,%1,%2,%3};"
        : "+f"(c[0]), "+f"(c[1]), "+f"(c[2]), "+f"(c[3])
        : "r"(a[0]), "r"(a[1]), "r"(a[2]), "r"(a[3]), "r"(b[0]), "r"(b[1]));
}
__device__ __forceinline__ void mma_f16(float* c, const uint32_t* a,
                                        const uint32_t* b) {
    asm volatile(
        "mma.sync.aligned.m16n8k16.row.col.f32.f16.f16.f32 "
        "{%0,%1,%2,%3}, {%4,%5,%6,%7}, {%8,%9}, {%0,%1,%2,%3};"
        : "+f"(c[0]), "+f"(c[1]), "+f"(c[2]), "+f"(c[3])
        : "r"(a[0]), "r"(a[1]), "r"(a[2]), "r"(a[3]), "r"(b[0]), "r"(b[1]));
}
__device__ __forceinline__ uint32_t packbf(__nv_bfloat16 a, __nv_bfloat16 b) {
    __nv_bfloat162 t = __halves2bfloat162(a, b);
    return *(uint32_t*)&t;
}
__device__ __forceinline__ uint32_t packh(float x, float y) {
    __half2 t = __floats2half2_rn(x, y);
    return *(uint32_t*)&t;
}
__device__ __forceinline__ void split2(float x, float y,
                                       uint32_t& hi, uint32_t& lo) {
    __nv_bfloat16 hx = __float2bfloat16(x), hy = __float2bfloat16(y);
    __nv_bfloat16 lx = __float2bfloat16(x - __bfloat162float(hx));
    __nv_bfloat16 ly = __float2bfloat16(y - __bfloat162float(hy));
    hi = packbf(hx, hy);
    lo = packbf(lx, ly);
}
__device__ __forceinline__ void splitf(float x, __nv_bfloat16& h, __nv_bfloat16& l) {
    h = __float2bfloat16(x);
    l = __float2bfloat16(x - __bfloat162float(h));
}

// ---------------------------------------------------------------------------
// Split fp32 -> bf16 hi/lo + fp16 single
// ---------------------------------------------------------------------------
__global__ void split3_kernel(const float* __restrict__ src,
                              __nv_bfloat16* __restrict__ hi,
                              __nv_bfloat16* __restrict__ lo,
                              __half* __restrict__ hf, int n4)
{
    int i = blockIdx.x * blockDim.x + threadIdx.x;
    if (i >= n4) return;
    float4 v = ((const float4*)src)[i];
    uint32_t h0, l0, h1, l1;
    split2(v.x, v.y, h0, l0);
    split2(v.z, v.w, h1, l1);
    ((uint32_t*)hi)[2*i]   = h0;
    ((uint32_t*)hi)[2*i+1] = h1;
    ((uint32_t*)lo)[2*i]   = l0;
    ((uint32_t*)lo)[2*i+1] = l1;
    ((uint32_t*)hf)[2*i]   = packh(v.x, v.y);
    ((uint32_t*)hf)[2*i+1] = packh(v.z, v.w);
}

// ---------------------------------------------------------------------------
// Transpose W[K,N] -> Wt[N,K], bf16 hi/lo
// ---------------------------------------------------------------------------
__global__ __launch_bounds__(256) void transpose_split_kernel(
    const float* __restrict__ W,
    __nv_bfloat16* __restrict__ hiT,
    __nv_bfloat16* __restrict__ loT, int K, int N)
{
    __shared__ float t[32][33];
    int n0 = blockIdx.x * 32, k0 = blockIdx.y * 32;
    int tx = threadIdx.x, ty = threadIdx.y;
#pragma unroll
    for (int r = 0; r < 4; r++)
        t[ty + r*8][tx] = W[(size_t)(k0 + ty + r*8) * N + n0 + tx];
    __syncthreads();
#pragma unroll
    for (int r = 0; r < 4; r++) {
        int n = n0 + ty + r*8;
        float v = t[tx][ty + r*8];
        __nv_bfloat16 h = __float2bfloat16(v);
        hiT[(size_t)n * K + k0 + tx] = h;
        loT[(size_t)n * K + k0 + tx] = __float2bfloat16(v - __bfloat162float(h));
    }
}

// Transpose W[K,N] -> Wt[N,K], single fp16
__global__ __launch_bounds__(256) void transpose_h_kernel(
    const float* __restrict__ W,
    __half* __restrict__ hT, int K, int N)
{
    __shared__ float t[32][33];
    int n0 = blockIdx.x * 32, k0 = blockIdx.y * 32;
    int tx = threadIdx.x, ty = threadIdx.y;
#pragma unroll
    for (int r = 0; r < 4; r++)
        t[ty + r*8][tx] = W[(size_t)(k0 + ty + r*8) * N + n0 + tx];
    __syncthreads();
#pragma unroll
    for (int r = 0; r < 4; r++) {
        int n = n0 + ty + r*8;
        hT[(size_t)n * K + k0 + tx] = __float2half_rn(t[tx][ty + r*8]);
    }
}

// ---------------------------------------------------------------------------
// Combined projection kernel: blockIdx.x < 20 -> QK bf16 3-term tile
// (N=2560, fp32 out); else -> V fp16 1-term tile (N=512, fp16 out). 2 CTAs/SM.
// ---------------------------------------------------------------------------
#define TSTRIDE 80
#define TILE_BYTES (128 * TSTRIDE)
#define STAGE_BYTES (4 * TILE_BYTES)
#define GEMM_SMEM (2 * STAGE_BYTES)

__device__ __forceinline__ void load_stage(
    uint32_t base, int tid,
    const __nv_bfloat16* Ah, const __nv_bfloat16* Al,
    const __nv_bfloat16* Bh, const __nv_bfloat16* Bl,
    int K, int k0)
{
    int ch = tid & 3;
    int rhalf = tid >> 2;
#pragma unroll
    for (int i = 0; i < 8; i++) {
        int tile = i >> 1;
        int row = (i & 1) * 64 + rhalf;
        uint32_t dst = base + tile * TILE_BYTES + row * TSTRIDE + ch * 16;
        const __nv_bfloat16* src =
            (tile == 0) ? Ah : (tile == 1) ? Al : (tile == 2) ? Bh : Bl;
        cp16(dst, src + (size_t)row * K + k0 + ch * 8);
    }
}

#define STAGE1_BYTES (2 * TILE_BYTES)

__device__ __forceinline__ void load_stage1(
    uint32_t base, int tid,
    const __half* A, const __half* Bh, int K, int k0)
{
    int ch = tid & 3;
    int rhalf = tid >> 2;
#pragma unroll
    for (int i = 0; i < 4; i++) {
        int tile = i >> 1;
        int row = (i & 1) * 64 + rhalf;
        uint32_t dst = base + tile * TILE_BYTES + row * TSTRIDE + ch * 16;
        const __half* src = (tile == 0) ? A : Bh;
        cp16(dst, src + (size_t)row * K + k0 + ch * 8);
    }
}

__global__ __launch_bounds__(256, 2) void qkv_proj_kernel()
{
    const int K = E;
    extern __shared__ char smem[];
    uint32_t sb = smem_u32(smem);
    int tid = threadIdx.x;
    int lane = tid & 31, wid = tid >> 5;
    int wm = wid & 1, wn = wid >> 1;
    int bm = blockIdx.y * 128;

    float acc[4][4][4];
#pragma unroll
    for (int i = 0; i < 4; i++)
#pragma unroll
        for (int j = 0; j < 4; j++)
#pragma unroll
            for (int r = 0; r < 4; r++) acc[i][j][r] = 0.f;

    uint32_t aoff = (uint32_t)((wm * 64 + (lane & 15)) * TSTRIDE + (lane >> 4) * 16);
    uint32_t boff = (uint32_t)((wn * 32 + ((lane >> 4) * 8) + (lane & 7)) * TSTRIDE
                               + ((lane >> 3) & 1) * 16);
    const int nch = K >> 5;

    if (blockIdx.x < 20) {
        int bn = blockIdx.x * 128;
        const __nv_bfloat16* Ah = g_xhi + (size_t)bm * K;
        const __nv_bfloat16* Al = g_xlo + (size_t)bm * K;
        const __nv_bfloat16* Bh = g_wqkhi + (size_t)bn * K;
        const __nv_bfloat16* Bl = g_wqklo + (size_t)bn * K;

        load_stage(sb, tid, Ah, Al, Bh, Bl, K, 0);
        cp_commit();

        for (int ch = 0; ch < nch; ch++) {
            if (ch + 1 < nch) {
                load_stage(sb + ((ch + 1) & 1) * STAGE_BYTES, tid,
                           Ah, Al, Bh, Bl, K, (ch + 1) << 5);
                cp_commit();
                cp_wait<1>();
            } else {
                cp_wait<0>();
            }
            __syncthreads();

            uint32_t st = sb + (ch & 1) * STAGE_BYTES;
            uint32_t sAhi = st;
            uint32_t sAlo = st + TILE_BYTES;
            uint32_t sBhi = st + 2 * TILE_BYTES;
            uint32_t sBlo = st + 3 * TILE_BYTES;

#pragma unroll
            for (int ks = 0; ks < 2; ks++) {
                uint32_t kb = ks * 32;
                uint32_t bh[8], bl[8], a[16];
                ldm4(bh + 0, sBhi + boff + kb);
                ldm4(bh + 4, sBhi + boff + 16 * TSTRIDE + kb);
                ldm4(bl + 0, sBlo + boff + kb);
                ldm4(bl + 4, sBlo + boff + 16 * TSTRIDE + kb);
#pragma unroll
                for (int mt = 0; mt < 4; mt++)
                    ldm4(a + 4 * mt, sAhi + aoff + mt * 16 * TSTRIDE + kb);
#pragma unroll
                for (int mt = 0; mt < 4; mt++)
#pragma unroll
                    for (int nt = 0; nt < 4; nt++)
                        mma_bf16(acc[mt][nt], a + 4 * mt, bh + 2 * nt);
#pragma unroll
                for (int mt = 0; mt < 4; mt++)
#pragma unroll
                    for (int nt = 0; nt < 4; nt++)
                        mma_bf16(acc[mt][nt], a + 4 * mt, bl + 2 * nt);
#pragma unroll
                for (int mt = 0; mt < 4; mt++)
                    ldm4(a + 4 * mt, sAlo + aoff + mt * 16 * TSTRIDE + kb);
#pragma unroll
                for (int mt = 0; mt < 4; mt++)
#pragma unroll
                    for (int nt = 0; nt < 4; nt++)
                        mma_bf16(acc[mt][nt], a + 4 * mt, bh + 2 * nt);
            }
            __syncthreads();
        }

        int r0 = bm + wm * 64 + (lane >> 2);
        int c0 = bn + wn * 32 + (lane & 3) * 2;
#pragma unroll
        for (int mt = 0; mt < 4; mt++) {
#pragma unroll
            for (int nt = 0; nt < 4; nt++) {
                int row = r0 + mt * 16;
                int col = c0 + nt * 8;
                *(float2*)&g_qk[(size_t)row * 2560 + col] =
                    make_float2(acc[mt][nt][0], acc[mt][nt][1]);
                *(float2*)&g_qk[(size_t)(row + 8) * 2560 + col] =
                    make_float2(acc[mt][nt][2], acc[mt][nt][3]);
            }
        }
    } else {
        int bn = (blockIdx.x - 20) * 128;
        const __half* Ap = g_xh + (size_t)bm * K;
        const __half* Bh = g_wvh + (size_t)bn * K;

        load_stage1(sb, tid, Ap, Bh, K, 0);
        cp_commit();

        for (int ch = 0; ch < nch; ch++) {
            if (ch + 1 < nch) {
                load_stage1(sb + ((ch + 1) & 1) * STAGE1_BYTES, tid,
                            Ap, Bh, K, (ch + 1) << 5);
                cp_commit();
                cp_wait<1>();
            } else {
                cp_wait<0>();
            }
            __syncthreads();

            uint32_t st = sb + (ch & 1) * STAGE1_BYTES;
            uint32_t sA = st;
            uint32_t sB = st + TILE_BYTES;

#pragma unroll
            for (int ks = 0; ks < 2; ks++) {
                uint32_t kb = ks * 32;
                uint32_t bh[8], a[16];
                ldm4(bh + 0, sB + boff + kb);
                ldm4(bh + 4, sB + boff + 16 * TSTRIDE + kb);
#pragma unroll
                for (int mt = 0; mt < 4; mt++)
                    ldm4(a + 4 * mt, sA + aoff + mt * 16 * TSTRIDE + kb);
#pragma unroll
                for (int mt = 0; mt < 4; mt++)
#pragma unroll
                    for (int nt = 0; nt < 4; nt++)
                        mma_f16(acc[mt][nt], a + 4 * mt, bh + 2 * nt);
            }
            __syncthreads();
        }

        int r0 = bm + wm * 64 + (lane >> 2);
        int c0 = bn + wn * 32 + (lane & 3) * 2;
#pragma unroll
        for (int mt = 0; mt < 4; mt++) {
#pragma unroll
            for (int nt = 0; nt < 4; nt++) {
                int row = r0 + mt * 16;
                int col = c0 + nt * 8;
                *(uint32_t*)&g_vh[(size_t)row * 512 + col] =
                    packh(acc[mt][nt][0], acc[mt][nt][1]);
                *(uint32_t*)&g_vh[(size_t)(row + 8) * 512 + col] =
                    packh(acc[mt][nt][2], acc[mt][nt][3]);
            }
        }
    }
}

// ---------------------------------------------------------------------------
// fp16 single-term GEMM (O-projection) — 2 CTAs/SM
// ---------------------------------------------------------------------------
#define GEMM1_SMEM (2 * STAGE1_BYTES)

__global__ __launch_bounds__(256, 2) void mma_gemm1_kernel(
    int M, int N, int K,
    const __half* __restrict__ A,
    const __half* __restrict__ Bhi,
    float* __restrict__ C)
{
    extern __shared__ char smem[];
    uint32_t sb = smem_u32(smem);
    int tid = threadIdx.x;
    int lane = tid & 31, wid = tid >> 5;
    int wm = wid & 1, wn = wid >> 1;
    int bm = blockIdx.y * 128, bn = blockIdx.x * 128;

    const __half* Ap = A + (size_t)bm * K;
    const __half* Bh = Bhi + (size_t)bn * K;

    float acc[4][4][4];
#pragma unroll
    for (int i = 0; i < 4; i++)
#pragma unroll
        for (int j = 0; j < 4; j++)
#pragma unroll
            for (int r = 0; r < 4; r++) acc[i][j][r] = 0.f;

    uint32_t aoff = (uint32_t)((wm * 64 + (lane & 15)) * TSTRIDE + (lane >> 4) * 16);
    uint32_t boff = (uint32_t)((wn * 32 + ((lane >> 4) * 8) + (lane & 7)) * TSTRIDE
                               + ((lane >> 3) & 1) * 16);

    const int nch = K >> 5;
    load_stage1(sb, tid, Ap, Bh, K, 0);
    cp_commit();

    for (int ch = 0; ch < nch; ch++) {
        if (ch + 1 < nch) {
            load_stage1(sb + ((ch + 1) & 1) * STAGE1_BYTES, tid,
                        Ap, Bh, K, (ch + 1) << 5);
            cp_commit();
            cp_wait<1>();
        } else {
            cp_wait<0>();
        }
        __syncthreads();

        uint32_t st = sb + (ch & 1) * STAGE1_BYTES;
        uint32_t sA = st;
        uint32_t sB = st + TILE_BYTES;

#pragma unroll
        for (int ks = 0; ks < 2; ks++) {
            uint32_t kb = ks * 32;
            uint32_t bh[8], a[16];
            ldm4(bh + 0, sB + boff + kb);
            ldm4(bh + 4, sB + boff + 16 * TSTRIDE + kb);
#pragma unroll
            for (int mt = 0; mt < 4; mt++)
                ldm4(a + 4 * mt, sA + aoff + mt * 16 * TSTRIDE + kb);
#pragma unroll
            for (int mt = 0; mt < 4; mt++)
#pragma unroll
                for (int nt = 0; nt < 4; nt++)
                    mma_f16(acc[mt][nt], a + 4 * mt, bh + 2 * nt);
        }
        __syncthreads();
    }

    int r0 = bm + wm * 64 + (lane >> 2);
    int c0 = bn + wn * 32 + (lane & 3) * 2;
#pragma unroll
    for (int mt = 0; mt < 4; mt++) {
#pragma unroll
        for (int nt = 0; nt < 4; nt++) {
            int row = r0 + mt * 16;
            int col = c0 + nt * 8;
            *(float2*)&C[(size_t)row * N + col] =
                make_float2(acc[mt][nt][0], acc[mt][nt][1]);
            *(float2*)&C[(size_t)(row + 8) * N + col] =
                make_float2(acc[mt][nt][2], acc[mt][nt][3]);
        }
    }
}

// ---------------------------------------------------------------------------
// Fused RoPE + bf16 hi/lo split over the fused q|k buffer (width 2560).
// Block-per-row mapping: no integer division, no bounds check; body math is
// bitwise-identical to the verified version.
// ---------------------------------------------------------------------------
__global__ __launch_bounds__(256) void rope_split_kernel(
    const float* __restrict__ qk,
    const float* __restrict__ cs,
    const float* __restrict__ sn)
{
    int row = blockIdx.x;            // 0 .. B*S-1
    int s = row & (S - 1);
    const float* rowp = qk + (size_t)row * 2560;

#pragma unroll
    for (int it = 0; it < 5; it++) {
        int pid = it * 256 + threadIdx.x;   // 0 .. 1279
        if (pid < 1024) {                 // q
            int h = pid >> 5, d = pid & 31;
            const float* base = rowp + h * 64;
            float v1 = base[d], v2 = base[d + 32];
            float c = cs[s * 32 + d], si = sn[s * 32 + d];
            float r1 = v1 * c - v2 * si;
            float r2 = v2 * c + v1 * si;
            __nv_bfloat16 h1, l1, h2, l2;
            splitf(r1, h1, l1); splitf(r2, h2, l2);
            size_t o = ((size_t)row * HQ + h) * 64 + d;
            g_qhi[o] = h1; g_qlo[o] = l1;
            g_qhi[o + 32] = h2; g_qlo[o + 32] = l2;
        } else {                          // k
            int kp = pid - 1024;
            int h = kp >> 5, d = kp & 31;
            const float* base = rowp + 2048 + h * 64;
            float v1 = base[d], v2 = base[d + 32];
            float c = cs[s * 32 + d], si = sn[s * 32 + d];
            float r1 = v1 * c - v2 * si;
            float r2 = v2 * c + v1 * si;
            __nv_bfloat16 h1, l1, h2, l2;
            splitf(r1, h1, l1); splitf(r2, h2, l2);
            size_t o = ((size_t)row * HK + h) * 64 + d;
            g_khi[o] = h1; g_klo[o] = l1;
            g_khi[o + 32] = h2; g_klo[o + 32] = l2;
        }
    }
}

// ---------------------------------------------------------------------------
// Tensor-core flash attention — 2 CTAs/SM (verified).
// QK: bf16 3-term. PV: p fp16 x v fp16 (1 term). fp16 out.
// ---------------------------------------------------------------------------
#define FSTRIDE 144
#define FTILE (64 * FSTRIDE)
#define FSTAGE (3 * FTILE)              // khi, klo, vh
#define QTILE (128 * FSTRIDE)
#define FLASH_SMEM (2 * FSTAGE)         // 55296

__global__ __launch_bounds__(256, 2) void flash_mma_kernel()
{
    extern __shared__ char smem[];
    uint32_t sb = smem_u32(smem);
    int tid = threadIdx.x;
    int lane = tid & 31, wq = tid >> 5;
    int qbase = blockIdx.x * 128;
    int h = blockIdx.y, b = blockIdx.z;
    int kh = h >> 2;

    // ---- stage Q hi/lo, build fragments ----
#pragma unroll
    for (int i = 0; i < 8; i++) {
        int lin = i * 256 + tid;
        int arr = lin >> 10;
        int rem = lin & 1023;
        int row = rem >> 3;
        int seg = rem & 7;
        const __nv_bfloat16* src = arr ? g_qlo : g_qhi;
        cp16(sb + arr * QTILE + row * FSTRIDE + seg * 16,
             src + ((size_t)(b * S + qbase + row) * HQ + h) * 64 + seg * 8);
    }
    cp_commit();
    cp_wait<0>();
    __syncthreads();

    uint32_t qhi[4][4], qlo[4][4];
    {
        uint32_t qoff = (uint32_t)((wq * 16 + (lane & 15)) * FSTRIDE + (lane >> 4) * 16);
#pragma unroll
        for (int ks = 0; ks < 4; ks++) {
            ldm4(qhi[ks], sb + qoff + ks * 32);
            ldm4(qlo[ks], sb + QTILE + qoff + ks * 32);
        }
    }
    __syncthreads();

    // ---- kv staging (3 arrays: khi, klo bf16; vh fp16) ----
    const uint8_t* srcs[3];
    srcs[0] = (const uint8_t*)(g_khi + ((size_t)b * S * HK + kh) * D);
    srcs[1] = (const uint8_t*)(g_klo + ((size_t)b * S * HK + kh) * D);
    srcs[2] = (const uint8_t*)(g_vh + ((size_t)b * S * HK + kh) * D);

    auto prefetch = [&](int t) {
        uint32_t base = sb + (t & 1) * FSTAGE;
        int key0 = t * 64;
#pragma unroll
        for (int i = 0; i < 6; i++) {
            int lin = i * 256 + tid;
            int arr = lin >> 9;
            int rem = lin & 511;
            int row = rem >> 3;
            int seg = rem & 7;
            cp16(base + arr * FTILE + row * FSTRIDE + seg * 16,
                 srcs[arr] + (size_t)(key0 + row) * (HK * D * 2) + seg * 16);
        }
        cp_commit();
    };

    uint32_t boff = (uint32_t)(((lane >> 4) * 8 + (lane & 7)) * FSTRIDE
                               + ((lane >> 3) & 1) * 16);
    uint32_t voff = (uint32_t)((lane & 15) * FSTRIDE + (lane >> 4) * 16);

    float o_[8][4];
#pragma unroll
    for (int nt = 0; nt < 8; nt++)
#pragma unroll
        for (int r = 0; r < 4; r++) o_[nt][r] = 0.f;
    float m0 = -1e30f, m1 = -1e30f, l0 = 0.f, l1 = 0.f;

    prefetch(0);

    const int NT = S / 64;
    for (int t = 0; t < NT; t++) {
        if (t + 1 < NT) { prefetch(t + 1); cp_wait<1>(); }
        else           { cp_wait<0>(); }
        __syncthreads();

        uint32_t st = sb + (t & 1) * FSTAGE;
        uint32_t sKhi = st, sKlo = st + FTILE;
        uint32_t sVh = st + 2 * FTILE;

        float s[8][4];
#pragma unroll
        for (int nt = 0; nt < 8; nt++)
#pragma unroll
            for (int r = 0; r < 4; r++) s[nt][r] = 0.f;

        // QK, processed in two 4-nt halves (reduced b-frag live range)
#pragma unroll
        for (int ks = 0; ks < 4; ks++) {
            uint32_t kb = ks * 32;
#pragma unroll
            for (int hf = 0; hf < 2; hf++) {
                uint32_t rb = hf * 32 * FSTRIDE;
                uint32_t bh[8], bl[8];
                ldm4(bh + 0, sKhi + boff + rb + kb);
                ldm4(bh + 4, sKhi + boff + rb + 16 * FSTRIDE + kb);
                ldm4(bl + 0, sKlo + boff + rb + kb);
                ldm4(bl + 4, sKlo + boff + rb + 16 * FSTRIDE + kb);
#pragma unroll
                for (int j = 0; j < 4; j++) {
                    int nt = hf * 4 + j;
                    mma_bf16(s[nt], qhi[ks], bh + 2*j);
                    mma_bf16(s[nt], qhi[ks], bl + 2*j);
                    mma_bf16(s[nt], qlo[ks], bh + 2*j);
                }
            }
        }

        float tmax0 = -1e30f, tmax1 = -1e30f;
#pragma unroll
        for (int nt = 0; nt < 8; nt++) {
            tmax0 = fmaxf(tmax0, fmaxf(s[nt][0], s[nt][1]));
            tmax1 = fmaxf(tmax1, fmaxf(s[nt][2], s[nt][3]));
        }
        tmax0 = fmaxf(tmax0, __shfl_xor_sync(0xffffffffu, tmax0, 1));
        tmax0 = fmaxf(tmax0, __shfl_xor_sync(0xffffffffu, tmax0, 2));
        tmax1 = fmaxf(tmax1, __shfl_xor_sync(0xffffffffu, tmax1, 1));
        tmax1 = fmaxf(tmax1, __shfl_xor_sync(0xffffffffu, tmax1, 2));
        float nm0 = fmaxf(m0, tmax0), nm1 = fmaxf(m1, tmax1);
        float a0 = __expf(m0 - nm0), a1 = __expf(m1 - nm1);
        m0 = nm0; m1 = nm1;
        float ps0 = 0.f, ps1 = 0.f;
#pragma unroll
        for (int nt = 0; nt < 8; nt++) {
            s[nt][0] = __expf(s[nt][0] - m0);
            s[nt][1] = __expf(s[nt][1] - m0);
            s[nt][2] = __expf(s[nt][2] - m1);
            s[nt][3] = __expf(s[nt][3] - m1);
            ps0 += s[nt][0] + s[nt][1];
            ps1 += s[nt][2] + s[nt][3];
        }
        l0 = l0 * a0 + ps0;
        l1 = l1 * a1 + ps1;
#pragma unroll
        for (int nt = 0; nt < 8; nt++) {
            o_[nt][0] *= a0; o_[nt][1] *= a0;
            o_[nt][2] *= a1; o_[nt][3] *= a1;
        }

        // ---- PV: p fp16 x v fp16, single term ----
#pragma unroll
        for (int ks = 0; ks < 4; ks++) {
            uint32_t ph[4];
            ph[0] = packh(s[2*ks][0],   s[2*ks][1]);
            ph[1] = packh(s[2*ks][2],   s[2*ks][3]);
            ph[2] = packh(s[2*ks+1][0], s[2*ks+1][1]);
            ph[3] = packh(s[2*ks+1][2], s[2*ks+1][3]);
            uint32_t rbase = ks * 16 * FSTRIDE;
#pragma unroll
            for (int n2 = 0; n2 < 4; n2++) {
                uint32_t vh[4];
                ldm4t(vh, sVh + voff + rbase + n2 * 32);
                mma_f16(o_[2*n2],     ph, vh + 0);
                mma_f16(o_[2*n2 + 1], ph, vh + 2);
            }
        }
        __syncthreads();
    }

    // ---- finalize: write single fp16 ----
    l0 += __shfl_xor_sync(0xffffffffu, l0, 1);
    l0 += __shfl_xor_sync(0xffffffffu, l0, 2);
    l1 += __shfl_xor_sync(0xffffffffu, l1, 1);
    l1 += __shfl_xor_sync(0xffffffffu, l1, 2);
    float inv0 = 1.f / l0, inv1 = 1.f / l1;

    int r = qbase + wq * 16 + (lane >> 2);
    int c = (lane & 3) * 2;
    size_t ob0 = ((size_t)(b * S + r) * HQ + h) * D;
    size_t ob1 = ((size_t)(b * S + r + 8) * HQ + h) * D;
#pragma unroll
    for (int nt = 0; nt < 8; nt++) {
        *(uint32_t*)(g_of + ob0 + nt * 8 + c) =
            packh(o_[nt][0] * inv0, o_[nt][1] * inv0);
        *(uint32_t*)(g_of + ob1 + nt * 8 + c) =
            packh(o_[nt][2] * inv1, o_[nt][3] * inv1);
    }
}

// ---------------------------------------------------------------------------
// Launch
// ---------------------------------------------------------------------------
extern "C" void kernel_launch(void* const* d_in, const int* in_sizes, int n_in,
                              void* d_out, int out_size)
{
    const float* x    = (const float*)d_in[0];
    const float* rcos = (const float*)d_in[1];
    const float* rsin = (const float*)d_in[2];
    const float* Wq   = (const float*)d_in[4];
    const float* Wk   = (const float*)d_in[5];
    const float* Wv   = (const float*)d_in[6];
    const float* Wo   = (const float*)d_in[7];
    float* out = (float*)d_out;

    float* qkp;
    cudaGetSymbolAddress((void**)&qkp, g_qk);
    __nv_bfloat16 *xhi, *xlo, *wqkhi, *wqklo;
    __half *xh, *wvh, *wohf, *ofp;
    cudaGetSymbolAddress((void**)&xhi, g_xhi);
    cudaGetSymbolAddress((void**)&xlo, g_xlo);
    cudaGetSymbolAddress((void**)&xh, g_xh);
    cudaGetSymbolAddress((void**)&wqkhi, g_wqkhi);
    cudaGetSymbolAddress((void**)&wqklo, g_wqklo);
    cudaGetSymbolAddress((void**)&wvh, g_wvh);
    cudaGetSymbolAddress((void**)&wohf, g_wohf);
    cudaGetSymbolAddress((void**)&ofp, g_of);

    cudaFuncSetAttribute(qkv_proj_kernel,
                         cudaFuncAttributeMaxDynamicSharedMemorySize, GEMM_SMEM);
    cudaFuncSetAttribute(mma_gemm1_kernel,
                         cudaFuncAttributeMaxDynamicSharedMemorySize, GEMM1_SMEM);
    cudaFuncSetAttribute(flash_mma_kernel,
                         cudaFuncAttributeMaxDynamicSharedMemorySize, FLASH_SMEM);

    const int M = B * S;  // 4096

    // 0) split x -> bf16 hi/lo + fp16
    {
        int n4 = M * E / 4;
        split3_kernel<<<(n4 + 255) / 256, 256>>>(x, xhi, xlo, xh, n4);
    }
    // 1-2) transpose+split Wq/Wk (bf16) into concatenated [2560, 2048]
    transpose_split_kernel<<<dim3((HQ*D)/32, E/32), dim3(32, 8)>>>(
        Wq, wqkhi, wqklo, E, HQ*D);
    transpose_split_kernel<<<dim3((HK*D)/32, E/32), dim3(32, 8)>>>(
        Wk, wqkhi + (size_t)2048 * E, wqklo + (size_t)2048 * E, E, HK*D);
    // 3) transpose Wv (fp16), 4) transpose Wo (fp16)
    transpose_h_kernel<<<dim3((HK*D)/32, E/32), dim3(32, 8)>>>(Wv, wvh, E, HK*D);
    transpose_h_kernel<<<dim3(E/32, (HQ*D)/32), dim3(32, 8)>>>(Wo, wohf, HQ*D, E);

    // 5) combined Q|K (bf16 3-term) + V (fp16 1-term) projection, one launch
    qkv_proj_kernel<<<dim3(24, M/128), 256, GEMM_SMEM>>>();

    // 6) fused RoPE + split (q,k only), block-per-row
    rope_split_kernel<<<B * S, 256>>>(qkp, rcos, rsin);

    // 7) tensor-core flash attention
    flash_mma_kernel<<<dim3(S / 128, HQ, B), 256, FLASH_SMEM>>>();

    // 8) O-projection (fp16, single term)
    mma_gemm1_kernel<<<dim3(E/128, M/128), 256, GEMM1_SMEM>>>(
        M, E, HQ*D, ofp, wohf, out);
}